// round 11
// baseline (speedup 1.0000x reference)
#include <cuda_runtime.h>
#include <cuda_fp16.h>
#include <cstdint>

// ===========================================================================
// SNN (20 steps, 2 fused Linear+LIF + feedback) on mma.sync (HMMA).
// Spikes = exactly 2^-11 in fp16; weights split into 2 fp16 limbs scaled by
// 2^11 -> products exact (fp32-identical trajectory).
// Round 11: readout absorbed into the persistent dataflow kernel as 32 extra
// tickets gated on cnt2[19][rb] -> overlaps with the step-19 tail and removes
// a launch boundary.
// ===========================================================================

#define BATCH   4096
#define DIM_D   1024
#define DIM_H1  2048
#define DIM_H2  1024
#define DIM_C   64
#define NUM_STEPS 20
#define BETA 0.9f
#define THRV 1.0f

#define RB_COUNT 32
#define L1_CB 16
#define L2_CB 8
#define TILES_PER_STEP (RB_COUNT * (L1_CB + L2_CB))        // 768
#define TOT_TILES (RB_COUNT * L2_CB + (NUM_STEPS - 1) * TILES_PER_STEP)  // 14848
#define TOT_ALL (TOT_TILES + RB_COUNT)                      // + 32 readout tiles

// ---------------------------------------------------------------------------
__device__ float  g_m1 [(size_t)BATCH * DIM_H1];
__device__ float  g_m2 [(size_t)BATCH * DIM_H2];
__device__ __half g_spk[(size_t)BATCH * DIM_H2];
__device__ __half g_s1 [(size_t)BATCH * DIM_H1];
__device__ __half g_s2 [(size_t)BATCH * DIM_H2];
__device__ __half g_w1h [(size_t)DIM_H1 * DIM_D];
__device__ __half g_w1l [(size_t)DIM_H1 * DIM_D];
__device__ __half g_w1hu[(size_t)DIM_H1 * DIM_D];
__device__ __half g_w2h [(size_t)DIM_H2 * DIM_H1];
__device__ __half g_w2l [(size_t)DIM_H2 * DIM_H1];
__device__ __half g_xh  [(size_t)BATCH * DIM_D];
__device__ __half g_xl  [(size_t)BATCH * DIM_D];
__device__ __half g_xhs [(size_t)BATCH * DIM_D];
__device__ unsigned g_ticket;
__device__ unsigned g_cnt1[NUM_STEPS][RB_COUNT];
__device__ unsigned g_cnt2[NUM_STEPS][RB_COUNT];

// ---------------------------------------------------------------------------
__device__ __forceinline__ uint32_t smem_u32(const void* p) {
    uint32_t a;
    asm("{ .reg .u64 t; cvta.to.shared.u64 t, %1; cvt.u32.u64 %0, t; }"
        : "=r"(a) : "l"(p));
    return a;
}
__device__ __forceinline__ void cp16(uint32_t dst, const void* src) {
    asm volatile("cp.async.cg.shared.global [%0], [%1], 16;"
                 :: "r"(dst), "l"(__cvta_generic_to_global(src)) : "memory");
}
__device__ __forceinline__ void ldsm4(uint32_t addr, uint32_t& r0, uint32_t& r1,
                                      uint32_t& r2, uint32_t& r3) {
    asm volatile("ldmatrix.sync.aligned.m8n8.x4.shared.b16 {%0,%1,%2,%3}, [%4];"
                 : "=r"(r0), "=r"(r1), "=r"(r2), "=r"(r3) : "r"(addr));
}
__device__ __forceinline__ void mma16816(float* c, const uint32_t a[4],
                                         uint32_t b0, uint32_t b1) {
    asm volatile(
        "mma.sync.aligned.m16n8k16.row.col.f32.f16.f16.f32 "
        "{%0,%1,%2,%3}, {%4,%5,%6,%7}, {%8,%9}, {%0,%1,%2,%3};"
        : "+f"(c[0]), "+f"(c[1]), "+f"(c[2]), "+f"(c[3])
        : "r"(a[0]), "r"(a[1]), "r"(a[2]), "r"(a[3]), "r"(b0), "r"(b1));
}

// ===========================================================================
// Persistent kernel: GEMM+LIF tiles + final readout tiles, one ticket queue.
// ===========================================================================
__global__ void __launch_bounds__(256, 2)
snn_persist(const __half* __restrict__ w1h, const __half* __restrict__ w1l,
            const __half* __restrict__ w2h, const __half* __restrict__ w2l,
            const float* __restrict__ b1, const float* __restrict__ b2,
            float* __restrict__ m1, float* __restrict__ m2,
            __half* __restrict__ s1, __half* __restrict__ s2,
            __half* __restrict__ spk_sum,
            const float* __restrict__ Wo, const float* __restrict__ bo,
            float* __restrict__ out)
{
    constexpr int TILE = 16384;
    constexpr int STAGE = 3 * TILE;
    extern __shared__ char smem[];
    unsigned* shdr = reinterpret_cast<unsigned*>(smem);
    const uint32_t sb = smem_u32(smem) + 1024;

    const int tid = threadIdx.x, lane = tid & 31, wid = tid >> 5;
    const int wm = wid >> 2, wn = wid & 3;

    const int arow = (lane & 7) + 8 * ((lane >> 3) & 1);
    const int asel = lane >> 4;
    const int brw  = (lane & 7) + 8 * (lane >> 4);
    const int bsel = (lane >> 3) & 1;
    const int sx   = lane & 7;
    const int qr   = lane >> 2, qc = (lane & 3) * 2;

    for (;;) {
        __syncthreads();
        if (tid == 0) shdr[0] = atomicAdd(&g_ticket, 1u);
        __syncthreads();
        const unsigned ti = shdr[0];
        if (ti >= TOT_ALL) break;

        // =================== READOUT TICKETS ===================
        if (ti >= TOT_TILES) {
            const int rb = (int)(ti - TOT_TILES);
            if (tid == 0) {
                volatile unsigned* dep = &g_cnt2[NUM_STEPS - 1][rb];
                while (*dep < L2_CB) __nanosleep(64);
            }
            __syncthreads();
            __threadfence();

            // smem: s fp16 [128 rows][128 k], pitch 272B; w fp32 [128 k][64 c]
            char*  s_sm = smem + 1024;                   // 34816 B
            float* w_sm = reinterpret_cast<float*>(smem + 1024 + 34816); // 32768 B
            const int rowbase = rb * 128;
            const int tr = tid & 31, tc = tid >> 5;
            const int c0 = tc * 8;

            float acc[4][8];
#pragma unroll
            for (int i = 0; i < 4; i++)
#pragma unroll
                for (int j = 0; j < 8; j++) acc[i][j] = 0.0f;

            for (int kc = 0; kc < DIM_H2 / 128; kc++) {
                const int k0 = kc * 128;
                __syncthreads();
                // stage s: 2048 x uint4, coalesced gmem, conflict-free STS
#pragma unroll
                for (int it = 0; it < 8; it++) {
                    int q = it * 256 + tid;
                    int r = q >> 4, kg = q & 15;
                    uint4 v = *reinterpret_cast<const uint4*>(
                        spk_sum + (size_t)(rowbase + r) * DIM_H2 + k0 + kg * 8);
                    *reinterpret_cast<uint4*>(s_sm + r * 272 + kg * 16) = v;
                }
                // stage w: [k][c] pitch 64; lanes take consecutive c
#pragma unroll
                for (int it = 0; it < 8; it++) {
                    int q = it * 256 + tid;
                    int kq = q >> 6, c = q & 63;
                    float4 v = *reinterpret_cast<const float4*>(
                        Wo + (size_t)c * DIM_H2 + k0 + kq * 4);
                    w_sm[(kq * 4 + 0) * 64 + c] = v.x;
                    w_sm[(kq * 4 + 1) * 64 + c] = v.y;
                    w_sm[(kq * 4 + 2) * 64 + c] = v.z;
                    w_sm[(kq * 4 + 3) * 64 + c] = v.w;
                }
                __syncthreads();

#pragma unroll 2
                for (int kg = 0; kg < 16; kg++) {
                    // s frags: 4 rows (tr + 32i), 8 halfs each
                    float fs[4][8];
#pragma unroll
                    for (int i = 0; i < 4; i++) {
                        uint4 v = *reinterpret_cast<const uint4*>(
                            s_sm + (tr + 32 * i) * 272 + kg * 16);
                        const __half2* h2 = reinterpret_cast<const __half2*>(&v);
#pragma unroll
                        for (int t = 0; t < 4; t++) {
                            float2 f = __half22float2(h2[t]);
                            fs[i][2 * t + 0] = f.x;
                            fs[i][2 * t + 1] = f.y;
                        }
                    }
#pragma unroll
                    for (int j8 = 0; j8 < 8; j8++) {
                        const int k = kg * 8 + j8;
                        float4 w0 = *reinterpret_cast<const float4*>(w_sm + k * 64 + c0);
                        float4 w1 = *reinterpret_cast<const float4*>(w_sm + k * 64 + c0 + 4);
                        float w8[8] = {w0.x, w0.y, w0.z, w0.w, w1.x, w1.y, w1.z, w1.w};
#pragma unroll
                        for (int i = 0; i < 4; i++)
#pragma unroll
                            for (int j = 0; j < 8; j++)
                                acc[i][j] = fmaf(fs[i][j8], w8[j], acc[i][j]);
                    }
                }
            }

#pragma unroll
            for (int i = 0; i < 4; i++) {
                const int row = rowbase + tr + 32 * i;
                float4 o0, o1;
                o0.x = acc[i][0] * (1.0f / NUM_STEPS) + bo[c0 + 0];
                o0.y = acc[i][1] * (1.0f / NUM_STEPS) + bo[c0 + 1];
                o0.z = acc[i][2] * (1.0f / NUM_STEPS) + bo[c0 + 2];
                o0.w = acc[i][3] * (1.0f / NUM_STEPS) + bo[c0 + 3];
                o1.x = acc[i][4] * (1.0f / NUM_STEPS) + bo[c0 + 4];
                o1.y = acc[i][5] * (1.0f / NUM_STEPS) + bo[c0 + 5];
                o1.z = acc[i][6] * (1.0f / NUM_STEPS) + bo[c0 + 6];
                o1.w = acc[i][7] * (1.0f / NUM_STEPS) + bo[c0 + 7];
                *reinterpret_cast<float4*>(out + (size_t)row * DIM_C + c0)     = o0;
                *reinterpret_cast<float4*>(out + (size_t)row * DIM_C + c0 + 4) = o1;
            }
            continue;
        }

        // =================== GEMM+LIF TICKETS ===================
        int t, layer, rb, cb;
        if (ti < RB_COUNT * L2_CB) {
            t = 0; layer = 2; rb = ti >> 3; cb = ti & 7;
        } else {
            const unsigned j = ti - RB_COUNT * L2_CB;
            t = 1 + (int)(j / TILES_PER_STEP);
            const unsigned r = j % TILES_PER_STEP;
            if (r < RB_COUNT * L1_CB) { layer = 1; rb = r >> 4; cb = r & 15; }
            else { const unsigned q = r - RB_COUNT * L1_CB; layer = 2; rb = q >> 3; cb = q & 7; }
        }

        if (tid == 0) {
            volatile unsigned* dep = nullptr;
            unsigned tgt = 0;
            if (layer == 1)      { dep = &g_cnt2[t - 1][rb]; tgt = L2_CB; }
            else if (t > 0)      { dep = &g_cnt1[t][rb];     tgt = L1_CB; }
            if (dep) while (*dep < tgt) __nanosleep(64);
        }
        __syncthreads();
        __threadfence();

        const int K = (layer == 1) ? DIM_H2 : DIM_H1;
        const int N = (layer == 1) ? DIM_H1 : DIM_H2;
        const __half* A  = (layer == 1) ? s2  : s1;
        const __half* W0 = (layer == 1) ? w1h : w2h;
        const __half* W1 = (layer == 1) ? w1l : w2l;
        const float* bias = (layer == 1) ? b1 : b2;
        float* mem = (layer == 1) ? m1 : m2;
        __half* spko = (layer == 1) ? s1 : s2;
        const bool SUMf = (layer == 2);
        const bool FIRSTf = (layer == 2) && (t == 0);
        const int brow = rb * 128, bcol = cb * 128;

        const __half* Ab = A + (size_t)brow * K;
        const __half* Wp0 = W0 + (size_t)bcol * K;
        const __half* Wp1 = W1 + (size_t)bcol * K;

        auto load_stage = [&](int st, int k0) {
            const uint32_t s0 = sb + st * STAGE;
            for (int q = tid; q < 1024; q += 256) {
                int r = q >> 3, c = q & 7;
                cp16(s0 + r * 128 + ((c ^ (r & 7)) << 4),
                     Ab + (size_t)r * K + k0 + c * 8);
            }
            for (int q = tid; q < 1024; q += 256) {
                int r = q >> 3, c = q & 7;
                cp16(s0 + TILE + r * 128 + ((c ^ (r & 7)) << 4),
                     Wp0 + (size_t)r * K + k0 + c * 8);
            }
            for (int q = tid; q < 1024; q += 256) {
                int r = q >> 3, c = q & 7;
                cp16(s0 + 2 * TILE + r * 128 + ((c ^ (r & 7)) << 4),
                     Wp1 + (size_t)r * K + k0 + c * 8);
            }
            asm volatile("cp.async.commit_group;" ::: "memory");
        };

        float acc[4][4][4];
#pragma unroll
        for (int i = 0; i < 4; i++)
#pragma unroll
            for (int j = 0; j < 4; j++)
#pragma unroll
                for (int k = 0; k < 4; k++) acc[i][j][k] = 0.0f;

        const int nch = K / 64;
        load_stage(0, 0);

        for (int ch = 0; ch < nch; ch++) {
            if (ch + 1 < nch) {
                load_stage((ch + 1) & 1, (ch + 1) * 64);
                asm volatile("cp.async.wait_group 1;" ::: "memory");
            } else {
                asm volatile("cp.async.wait_group 0;" ::: "memory");
            }
            __syncthreads();

            const uint32_t s0 = sb + (ch & 1) * STAGE;
            uint32_t bb[2][2];
#pragma unroll
            for (int w = 0; w < 2; w++)
#pragma unroll
                for (int h = 0; h < 2; h++)
                    bb[w][h] = s0 + (1 + w) * TILE + (wn * 32 + h * 16 + brw) * 128;

#pragma unroll
            for (int ks = 0; ks < 4; ks++) {
                uint32_t b[2][8];
#pragma unroll
                for (int w = 0; w < 2; w++) {
                    const uint32_t off = ((2 * ks + bsel) ^ sx) << 4;
                    ldsm4(bb[w][0] + off, b[w][0], b[w][1], b[w][2], b[w][3]);
                    ldsm4(bb[w][1] + off, b[w][4], b[w][5], b[w][6], b[w][7]);
                }
                const uint32_t aoff = ((2 * ks + asel) ^ sx) << 4;
                uint32_t a[4][4];
#pragma unroll
                for (int mf = 0; mf < 4; mf++)
                    ldsm4(s0 + (wm * 64 + mf * 16 + arow) * 128 + aoff,
                          a[mf][0], a[mf][1], a[mf][2], a[mf][3]);
#pragma unroll
                for (int w = 0; w < 2; w++)
#pragma unroll
                    for (int mf = 0; mf < 4; mf++)
#pragma unroll
                        for (int nf = 0; nf < 4; nf++)
                            mma16816(acc[mf][nf], a[mf], b[w][2 * nf], b[w][2 * nf + 1]);
            }
            __syncthreads();
        }

#pragma unroll
        for (int mf = 0; mf < 4; mf++)
#pragma unroll
        for (int h = 0; h < 2; h++) {
            const int row = brow + wm * 64 + mf * 16 + qr + 8 * h;
#pragma unroll
            for (int nf = 0; nf < 4; nf++) {
                const int col = bcol + wn * 32 + nf * 8 + qc;
                const size_t ix = (size_t)row * N + col;
                float2 bb = *reinterpret_cast<const float2*>(bias + col);
                float v0 = acc[mf][nf][2 * h + 0] + bb.x;
                float v1 = acc[mf][nf][2 * h + 1] + bb.y;
                float m0, m1v;
                if (FIRSTf) {
                    m0 = v0; m1v = v1;
                } else {
                    float2 mo = *reinterpret_cast<const float2*>(mem + ix);
                    m0  = BETA * mo.x + v0 - ((mo.x > THRV) ? THRV : 0.0f);
                    m1v = BETA * mo.y + v1 - ((mo.y > THRV) ? THRV : 0.0f);
                }
                const bool sp0 = m0 > THRV, sp1 = m1v > THRV;
                *reinterpret_cast<float2*>(mem + ix) = make_float2(m0, m1v);
                uint32_t sv = (sp0 ? 0x1000u : 0u) | (sp1 ? 0x10000000u : 0u);
                *reinterpret_cast<uint32_t*>(spko + ix) = sv;
                if (SUMf) {
                    __half2 add = __floats2half2_rn(sp0 ? 1.0f : 0.0f,
                                                    sp1 ? 1.0f : 0.0f);
                    __half2* ss = reinterpret_cast<__half2*>(spk_sum + ix);
                    if (FIRSTf) *ss = add;
                    else        *ss = __hadd2(*ss, add);
                }
            }
        }

        __threadfence();
        __syncthreads();
        if (tid == 0) {
            unsigned* rel = (layer == 1) ? &g_cnt1[t][rb] : &g_cnt2[t][rb];
            atomicAdd(rel, 1u);
        }
    }
}

// ===========================================================================
// t=0 layer-1 kernel (real-valued x, 3 fp16 limb products). Runs once.
// ===========================================================================
__global__ void __launch_bounds__(256, 2)
snn_tz(const __half* __restrict__ A0, const __half* __restrict__ A1,
       const __half* __restrict__ A2,
       const __half* __restrict__ W0, const __half* __restrict__ W1,
       const float* __restrict__ bias, float* __restrict__ mem,
       __half* __restrict__ spk, int N, int K)
{
    constexpr int FT = 16384;
    constexpr int FSTAGE = 5 * FT;
    extern __shared__ char smem[];
    const uint32_t sb = smem_u32(smem);

    const int tid = threadIdx.x, lane = tid & 31, wid = tid >> 5;
    const int wm = wid >> 2, wn = wid & 3;
    const int brow = blockIdx.y * 128, bcol = blockIdx.x * 128;

    const __half* Ap[3] = { A0 + (size_t)brow * K, A1 + (size_t)brow * K,
                            A2 + (size_t)brow * K };
    const __half* Wp[2] = { W0 + (size_t)bcol * K, W1 + (size_t)bcol * K };

    auto load_stage = [&](int st, int k0) {
        const uint32_t s0 = sb + st * FSTAGE;
#pragma unroll
        for (int l = 0; l < 3; l++) {
            const uint32_t d = s0 + l * FT;
            for (int q = tid; q < 1024; q += 256) {
                int r = q >> 3, c = q & 7;
                cp16(d + r * 128 + ((c ^ (r & 7)) << 4),
                     Ap[l] + (size_t)r * K + k0 + c * 8);
            }
        }
#pragma unroll
        for (int l = 0; l < 2; l++) {
            const uint32_t d = s0 + (3 + l) * FT;
            for (int q = tid; q < 1024; q += 256) {
                int r = q >> 3, c = q & 7;
                cp16(d + r * 128 + ((c ^ (r & 7)) << 4),
                     Wp[l] + (size_t)r * K + k0 + c * 8);
            }
        }
        asm volatile("cp.async.commit_group;" ::: "memory");
    };

    const int arow = (lane & 7) + 8 * ((lane >> 3) & 1);
    const int asel = lane >> 4;
    const int brw  = (lane & 7) + 8 * (lane >> 4);
    const int bsel = (lane >> 3) & 1;
    const int sx   = lane & 7;

    float acc[4][4][4];
#pragma unroll
    for (int i = 0; i < 4; i++)
#pragma unroll
        for (int j = 0; j < 4; j++)
#pragma unroll
            for (int k = 0; k < 4; k++) acc[i][j][k] = 0.0f;

    const int nch = K / 64;
    load_stage(0, 0);

    for (int ch = 0; ch < nch; ch++) {
        asm volatile("cp.async.wait_group 0;" ::: "memory");
        __syncthreads();
        if (ch + 1 < nch) load_stage((ch + 1) & 1, (ch + 1) * 64);

        const uint32_t s0 = sb + (ch & 1) * FSTAGE;
#pragma unroll
        for (int ks = 0; ks < 4; ks++) {
            const uint32_t aoff = ((2 * ks + asel) ^ sx) << 4;
            const uint32_t boff = ((2 * ks + bsel) ^ sx) << 4;
            uint32_t b[2][8];
#pragma unroll
            for (int w = 0; w < 2; w++) {
                const uint32_t bw = s0 + (3 + w) * FT + (wn * 32 + brw) * 128 + boff;
                ldsm4(bw, b[w][0], b[w][1], b[w][2], b[w][3]);
                ldsm4(bw + 16 * 128, b[w][4], b[w][5], b[w][6], b[w][7]);
            }
            const int PA[3] = {0, 1, 2}, PW[3] = {0, 1, 0};
#pragma unroll
            for (int p = 0; p < 3; p++) {
                uint32_t a[4][4];
#pragma unroll
                for (int mf = 0; mf < 4; mf++)
                    ldsm4(s0 + PA[p] * FT + (wm * 64 + mf * 16 + arow) * 128 + aoff,
                          a[mf][0], a[mf][1], a[mf][2], a[mf][3]);
#pragma unroll
                for (int mf = 0; mf < 4; mf++)
#pragma unroll
                    for (int nf = 0; nf < 4; nf++)
                        mma16816(acc[mf][nf], a[mf], b[PW[p]][2 * nf], b[PW[p]][2 * nf + 1]);
            }
        }
        __syncthreads();
    }

    const int qr = lane >> 2, qc = (lane & 3) * 2;
#pragma unroll
    for (int mf = 0; mf < 4; mf++)
#pragma unroll
    for (int h2 = 0; h2 < 2; h2++) {
        const int row = brow + wm * 64 + mf * 16 + qr + 8 * h2;
#pragma unroll
        for (int nf = 0; nf < 4; nf++) {
            const int col = bcol + wn * 32 + nf * 8 + qc;
            const size_t ix = (size_t)row * N + col;
            float2 bb = *reinterpret_cast<const float2*>(bias + col);
            float m0  = acc[mf][nf][2 * h2 + 0] + bb.x;
            float m1v = acc[mf][nf][2 * h2 + 1] + bb.y;
            const bool sp0 = m0 > THRV, sp1 = m1v > THRV;
            *reinterpret_cast<float2*>(mem + ix) = make_float2(m0, m1v);
            uint32_t sv = (sp0 ? 0x1000u : 0u) | (sp1 ? 0x10000000u : 0u);
            *reinterpret_cast<uint32_t*>(spk + ix) = sv;
        }
    }
}

// ---------------------------------------------------------------------------
// Fused prep: weight/x splits + scheduler reset.
// ---------------------------------------------------------------------------
#define N_W1 (DIM_H1 * DIM_D)
#define N_W2 (DIM_H2 * DIM_H1)
#define N_X  (BATCH * DIM_D)

__global__ void __launch_bounds__(256)
prep_all(const float* __restrict__ W1, const float* __restrict__ W2,
         const float* __restrict__ x,
         __half* __restrict__ w1h, __half* __restrict__ w1l,
         __half* __restrict__ w1hu,
         __half* __restrict__ w2h, __half* __restrict__ w2l,
         __half* __restrict__ xh, __half* __restrict__ xl,
         __half* __restrict__ xhs)
{
    if (blockIdx.x == 0) {
        for (int z = threadIdx.x; z < NUM_STEPS * RB_COUNT; z += 256) {
            (&g_cnt1[0][0])[z] = 0u;
            (&g_cnt2[0][0])[z] = 0u;
        }
        if (threadIdx.x == 0) g_ticket = 0u;
    }
    const int total = N_W1 + N_W2 + N_X;
    for (int i = blockIdx.x * 256 + threadIdx.x; i < total; i += gridDim.x * 256) {
        if (i < N_W1) {
            float v = W1[i] * 2048.0f;
            __half h = __float2half_rn(v);
            w1h[i] = h;
            w1l[i] = __float2half_rn(v - __half2float(h));
            w1hu[i] = __float2half_rn(__half2float(h) * (1.0f / 2048.0f));
        } else if (i < N_W1 + N_W2) {
            int j = i - N_W1;
            float v = W2[j] * 2048.0f;
            __half h = __float2half_rn(v);
            w2h[j] = h;
            w2l[j] = __float2half_rn(v - __half2float(h));
        } else {
            int j = i - N_W1 - N_W2;
            float v = x[j];
            __half h = __float2half_rn(v);
            xh[j] = h;
            xl[j] = __float2half_rn(v - __half2float(h));
            xhs[j] = __float2half_rn(__half2float(h) * (1.0f / 2048.0f));
        }
    }
}

// ---------------------------------------------------------------------------
extern "C" void kernel_launch(void* const* d_in, const int* in_sizes, int n_in,
                              void* d_out, int out_size)
{
    const float* x  = (const float*)d_in[0];
    const float* W1 = (const float*)d_in[1];
    const float* b1 = (const float*)d_in[2];
    const float* W2 = (const float*)d_in[3];
    const float* b2 = (const float*)d_in[4];
    const float* Wo = (const float*)d_in[5];
    const float* bo = (const float*)d_in[6];
    float* out = (float*)d_out;

    auto sym = [](const void* s) { void* p; cudaGetSymbolAddress(&p, s); return p; };
    float*  m1   = (float*)sym(g_m1);
    float*  m2   = (float*)sym(g_m2);
    __half* spk  = (__half*)sym(g_spk);
    __half* s1   = (__half*)sym(g_s1);
    __half* s2   = (__half*)sym(g_s2);
    __half* w1h  = (__half*)sym(g_w1h);
    __half* w1l  = (__half*)sym(g_w1l);
    __half* w1hu = (__half*)sym(g_w1hu);
    __half* w2h  = (__half*)sym(g_w2h);
    __half* w2l  = (__half*)sym(g_w2l);
    __half* xh   = (__half*)sym(g_xh);
    __half* xl   = (__half*)sym(g_xl);
    __half* xhs  = (__half*)sym(g_xhs);

    constexpr int SM_PS = 1024 + 2 * 3 * 16384;   //  99328 -> 2 CTA/SM
    constexpr int SM_TZ = 2 * 5 * 16384;          // 163840 -> 1 CTA/SM
    cudaFuncSetAttribute(snn_tz, cudaFuncAttributeMaxDynamicSharedMemorySize, SM_TZ);
    cudaFuncSetAttribute(snn_persist, cudaFuncAttributeMaxDynamicSharedMemorySize, SM_PS);

    int nsm = 0, occ = 0;
    cudaDeviceGetAttribute(&nsm, cudaDevAttrMultiProcessorCount, 0);
    cudaOccupancyMaxActiveBlocksPerMultiprocessor(&occ, snn_persist, 256, SM_PS);
    if (occ < 1) occ = 1;
    if (occ > 2) occ = 2;
    const int pgrid = nsm * occ;

    prep_all<<<2048, 256>>>(W1, W2, x, w1h, w1l, w1hu, w2h, w2l, xh, xl, xhs);

    dim3 gtz(DIM_H1 / 128, BATCH / 128);
    snn_tz<<<gtz, 256, SM_TZ>>>(xh, xhs, xl, w1hu, w1l, b1, m1, s1, DIM_H1, DIM_D);

    snn_persist<<<pgrid, 256, SM_PS>>>(w1h, w1l, w2h, w2l, b1, b2,
                                       m1, m2, s1, s2, spk, Wo, bo, out);
}

// round 12
// speedup vs baseline: 1.0795x; 1.0795x over previous
#include <cuda_runtime.h>
#include <cuda_fp16.h>
#include <cstdint>

// ===========================================================================
// SNN (20 steps, 2 fused Linear+LIF + feedback) on mma.sync (HMMA).
// Spikes = exactly 2^-11 in fp16; weights split into 2 fp16 limbs scaled by
// 2^11 -> products exact (fp32-identical trajectory).
// Round 12: readout folded into the persistent kernel as HMMA tickets that
// REUSE the unchanged GEMM mainloop (spk_sum scaled 2^-11, Wo 2-limb padded
// to 128 rows); only the epilogue branches. R11's heavy FFMA branch reverted.
// ===========================================================================

#define BATCH   4096
#define DIM_D   1024
#define DIM_H1  2048
#define DIM_H2  1024
#define DIM_C   64
#define NUM_STEPS 20
#define BETA 0.9f
#define THRV 1.0f

#define RB_COUNT 32
#define L1_CB 16
#define L2_CB 8
#define TILES_PER_STEP (RB_COUNT * (L1_CB + L2_CB))        // 768
#define TOT_TILES (RB_COUNT * L2_CB + (NUM_STEPS - 1) * TILES_PER_STEP)  // 14848
#define TOT_ALL (TOT_TILES + RB_COUNT)                      // +32 readout tiles

// ---------------------------------------------------------------------------
__device__ float  g_m1 [(size_t)BATCH * DIM_H1];
__device__ float  g_m2 [(size_t)BATCH * DIM_H2];
__device__ __half g_spk[(size_t)BATCH * DIM_H2];    // spike counts * 2^-11
__device__ __half g_s1 [(size_t)BATCH * DIM_H1];
__device__ __half g_s2 [(size_t)BATCH * DIM_H2];
__device__ __half g_w1h [(size_t)DIM_H1 * DIM_D];
__device__ __half g_w1l [(size_t)DIM_H1 * DIM_D];
__device__ __half g_w1hu[(size_t)DIM_H1 * DIM_D];
__device__ __half g_w2h [(size_t)DIM_H2 * DIM_H1];
__device__ __half g_w2l [(size_t)DIM_H2 * DIM_H1];
__device__ __half g_woh [(size_t)128 * DIM_H2];     // Wo*2^11 hi limb (padded)
__device__ __half g_wol [(size_t)128 * DIM_H2];     // Wo*2^11 lo limb (padded)
__device__ __half g_xh  [(size_t)BATCH * DIM_D];
__device__ __half g_xl  [(size_t)BATCH * DIM_D];
__device__ __half g_xhs [(size_t)BATCH * DIM_D];
__device__ unsigned g_ticket;
__device__ unsigned g_cnt1[NUM_STEPS][RB_COUNT];
__device__ unsigned g_cnt2[NUM_STEPS][RB_COUNT];

// ---------------------------------------------------------------------------
__device__ __forceinline__ uint32_t smem_u32(const void* p) {
    uint32_t a;
    asm("{ .reg .u64 t; cvta.to.shared.u64 t, %1; cvt.u32.u64 %0, t; }"
        : "=r"(a) : "l"(p));
    return a;
}
__device__ __forceinline__ void cp16(uint32_t dst, const void* src) {
    asm volatile("cp.async.cg.shared.global [%0], [%1], 16;"
                 :: "r"(dst), "l"(__cvta_generic_to_global(src)) : "memory");
}
__device__ __forceinline__ void ldsm4(uint32_t addr, uint32_t& r0, uint32_t& r1,
                                      uint32_t& r2, uint32_t& r3) {
    asm volatile("ldmatrix.sync.aligned.m8n8.x4.shared.b16 {%0,%1,%2,%3}, [%4];"
                 : "=r"(r0), "=r"(r1), "=r"(r2), "=r"(r3) : "r"(addr));
}
__device__ __forceinline__ void mma16816(float* c, const uint32_t a[4],
                                         uint32_t b0, uint32_t b1) {
    asm volatile(
        "mma.sync.aligned.m16n8k16.row.col.f32.f16.f16.f32 "
        "{%0,%1,%2,%3}, {%4,%5,%6,%7}, {%8,%9}, {%0,%1,%2,%3};"
        : "+f"(c[0]), "+f"(c[1]), "+f"(c[2]), "+f"(c[3])
        : "r"(a[0]), "r"(a[1]), "r"(a[2]), "r"(a[3]), "r"(b0), "r"(b1));
}

// ===========================================================================
// Persistent kernel: GEMM+LIF tiles + readout tiles via the SAME mainloop.
// layer: 1 = L1 GEMM+LIF, 2 = L2 GEMM+LIF(+sum), 3 = readout GEMM.
// ===========================================================================
__global__ void __launch_bounds__(256, 2)
snn_persist(const __half* __restrict__ w1h, const __half* __restrict__ w1l,
            const __half* __restrict__ w2h, const __half* __restrict__ w2l,
            const float* __restrict__ b1, const float* __restrict__ b2,
            float* __restrict__ m1, float* __restrict__ m2,
            __half* __restrict__ s1, __half* __restrict__ s2,
            __half* __restrict__ spk_sum,
            const __half* __restrict__ woh, const __half* __restrict__ wol,
            const float* __restrict__ bo, float* __restrict__ out)
{
    constexpr int TILE = 16384;
    constexpr int STAGE = 3 * TILE;
    extern __shared__ char smem[];
    unsigned* shdr = reinterpret_cast<unsigned*>(smem);
    const uint32_t sb = smem_u32(smem) + 1024;

    const int tid = threadIdx.x, lane = tid & 31, wid = tid >> 5;
    const int wm = wid >> 2, wn = wid & 3;

    const int arow = (lane & 7) + 8 * ((lane >> 3) & 1);
    const int asel = lane >> 4;
    const int brw  = (lane & 7) + 8 * (lane >> 4);
    const int bsel = (lane >> 3) & 1;
    const int sx   = lane & 7;
    const int qr   = lane >> 2, qc = (lane & 3) * 2;

    for (;;) {
        __syncthreads();
        if (tid == 0) shdr[0] = atomicAdd(&g_ticket, 1u);
        __syncthreads();
        const unsigned ti = shdr[0];
        if (ti >= TOT_ALL) break;

        int t, layer, rb, cb;
        if (ti >= TOT_TILES) {
            layer = 3; t = NUM_STEPS - 1; rb = (int)(ti - TOT_TILES); cb = 0;
        } else if (ti < RB_COUNT * L2_CB) {
            t = 0; layer = 2; rb = ti >> 3; cb = ti & 7;
        } else {
            const unsigned j = ti - RB_COUNT * L2_CB;
            t = 1 + (int)(j / TILES_PER_STEP);
            const unsigned r = j % TILES_PER_STEP;
            if (r < RB_COUNT * L1_CB) { layer = 1; rb = r >> 4; cb = r & 15; }
            else { const unsigned q = r - RB_COUNT * L1_CB; layer = 2; rb = q >> 3; cb = q & 7; }
        }

        if (tid == 0) {
            volatile unsigned* dep = nullptr;
            unsigned tgt = 0;
            if (layer == 1)      { dep = &g_cnt2[t - 1][rb]; tgt = L2_CB; }
            else if (layer == 3) { dep = &g_cnt2[NUM_STEPS - 1][rb]; tgt = L2_CB; }
            else if (t > 0)      { dep = &g_cnt1[t][rb];     tgt = L1_CB; }
            if (dep) while (*dep < tgt) __nanosleep(64);
        }
        __syncthreads();
        __threadfence();

        // ---- per-tile parameters (mainloop is identical for all layers) ----
        const int K = (layer == 2) ? DIM_H1 : DIM_H2;       // 2048 : 1024
        const __half* A  = (layer == 1) ? s2 : (layer == 2) ? s1 : spk_sum;
        const __half* W0 = (layer == 1) ? w1h : (layer == 2) ? w2h : woh;
        const __half* W1 = (layer == 1) ? w1l : (layer == 2) ? w2l : wol;
        const int brow = rb * 128, bcol = cb * 128;

        const __half* Ab = A + (size_t)brow * K;
        const __half* Wp0 = W0 + (size_t)bcol * K;
        const __half* Wp1 = W1 + (size_t)bcol * K;

        auto load_stage = [&](int st, int k0) {
            const uint32_t s0 = sb + st * STAGE;
            for (int q = tid; q < 1024; q += 256) {
                int r = q >> 3, c = q & 7;
                cp16(s0 + r * 128 + ((c ^ (r & 7)) << 4),
                     Ab + (size_t)r * K + k0 + c * 8);
            }
            for (int q = tid; q < 1024; q += 256) {
                int r = q >> 3, c = q & 7;
                cp16(s0 + TILE + r * 128 + ((c ^ (r & 7)) << 4),
                     Wp0 + (size_t)r * K + k0 + c * 8);
            }
            for (int q = tid; q < 1024; q += 256) {
                int r = q >> 3, c = q & 7;
                cp16(s0 + 2 * TILE + r * 128 + ((c ^ (r & 7)) << 4),
                     Wp1 + (size_t)r * K + k0 + c * 8);
            }
            asm volatile("cp.async.commit_group;" ::: "memory");
        };

        float acc[4][4][4];
#pragma unroll
        for (int i = 0; i < 4; i++)
#pragma unroll
            for (int j = 0; j < 4; j++)
#pragma unroll
                for (int k = 0; k < 4; k++) acc[i][j][k] = 0.0f;

        const int nch = K / 64;
        load_stage(0, 0);

        for (int ch = 0; ch < nch; ch++) {
            if (ch + 1 < nch) {
                load_stage((ch + 1) & 1, (ch + 1) * 64);
                asm volatile("cp.async.wait_group 1;" ::: "memory");
            } else {
                asm volatile("cp.async.wait_group 0;" ::: "memory");
            }
            __syncthreads();

            const uint32_t s0 = sb + (ch & 1) * STAGE;
            uint32_t bb[2][2];
#pragma unroll
            for (int w = 0; w < 2; w++)
#pragma unroll
                for (int h = 0; h < 2; h++)
                    bb[w][h] = s0 + (1 + w) * TILE + (wn * 32 + h * 16 + brw) * 128;

#pragma unroll
            for (int ks = 0; ks < 4; ks++) {
                uint32_t b[2][8];
#pragma unroll
                for (int w = 0; w < 2; w++) {
                    const uint32_t off = ((2 * ks + bsel) ^ sx) << 4;
                    ldsm4(bb[w][0] + off, b[w][0], b[w][1], b[w][2], b[w][3]);
                    ldsm4(bb[w][1] + off, b[w][4], b[w][5], b[w][6], b[w][7]);
                }
                const uint32_t aoff = ((2 * ks + asel) ^ sx) << 4;
                uint32_t a[4][4];
#pragma unroll
                for (int mf = 0; mf < 4; mf++)
                    ldsm4(s0 + (wm * 64 + mf * 16 + arow) * 128 + aoff,
                          a[mf][0], a[mf][1], a[mf][2], a[mf][3]);
#pragma unroll
                for (int w = 0; w < 2; w++)
#pragma unroll
                    for (int mf = 0; mf < 4; mf++)
#pragma unroll
                        for (int nf = 0; nf < 4; nf++)
                            mma16816(acc[mf][nf], a[mf], b[w][2 * nf], b[w][2 * nf + 1]);
            }
            __syncthreads();
        }

        // ---- epilogues ----
        if (layer == 3) {
            // out[row, col] = acc / NUM_STEPS + bo[col], cols 0..63 only.
#pragma unroll
            for (int mf = 0; mf < 4; mf++)
#pragma unroll
            for (int h = 0; h < 2; h++) {
                const int row = brow + wm * 64 + mf * 16 + qr + 8 * h;
#pragma unroll
                for (int nf = 0; nf < 4; nf++) {
                    const int col = wn * 32 + nf * 8 + qc;
                    if (col < DIM_C) {
                        float2 bb2 = *reinterpret_cast<const float2*>(bo + col);
                        float2 o;
                        o.x = acc[mf][nf][2 * h + 0] * (1.0f / NUM_STEPS) + bb2.x;
                        o.y = acc[mf][nf][2 * h + 1] * (1.0f / NUM_STEPS) + bb2.y;
                        *reinterpret_cast<float2*>(out + (size_t)row * DIM_C + col) = o;
                    }
                }
            }
            continue;
        }

        const int N = (layer == 1) ? DIM_H1 : DIM_H2;
        const float* bias = (layer == 1) ? b1 : b2;
        float* mem = (layer == 1) ? m1 : m2;
        __half* spko = (layer == 1) ? s1 : s2;
        const bool SUMf = (layer == 2);
        const bool FIRSTf = (layer == 2) && (t == 0);

#pragma unroll
        for (int mf = 0; mf < 4; mf++)
#pragma unroll
        for (int h = 0; h < 2; h++) {
            const int row = brow + wm * 64 + mf * 16 + qr + 8 * h;
#pragma unroll
            for (int nf = 0; nf < 4; nf++) {
                const int col = bcol + wn * 32 + nf * 8 + qc;
                const size_t ix = (size_t)row * N + col;
                float2 bb = *reinterpret_cast<const float2*>(bias + col);
                float v0 = acc[mf][nf][2 * h + 0] + bb.x;
                float v1 = acc[mf][nf][2 * h + 1] + bb.y;
                float m0, m1v;
                if (FIRSTf) {
                    m0 = v0; m1v = v1;
                } else {
                    float2 mo = *reinterpret_cast<const float2*>(mem + ix);
                    m0  = BETA * mo.x + v0 - ((mo.x > THRV) ? THRV : 0.0f);
                    m1v = BETA * mo.y + v1 - ((mo.y > THRV) ? THRV : 0.0f);
                }
                const bool sp0 = m0 > THRV, sp1 = m1v > THRV;
                *reinterpret_cast<float2*>(mem + ix) = make_float2(m0, m1v);
                uint32_t sv = (sp0 ? 0x1000u : 0u) | (sp1 ? 0x10000000u : 0u);
                *reinterpret_cast<uint32_t*>(spko + ix) = sv;
                if (SUMf) {
                    // accumulate counts * 2^-11 (0x1000 = 2^-11 in fp16, exact)
                    __half2 add;
                    uint32_t au = (sp0 ? 0x1000u : 0u) | (sp1 ? 0x10000000u : 0u);
                    add = *reinterpret_cast<__half2*>(&au);
                    __half2* ss = reinterpret_cast<__half2*>(spk_sum + ix);
                    if (FIRSTf) *ss = add;
                    else        *ss = __hadd2(*ss, add);
                }
            }
        }

        __threadfence();
        __syncthreads();
        if (tid == 0) {
            unsigned* rel = (layer == 1) ? &g_cnt1[t][rb] : &g_cnt2[t][rb];
            atomicAdd(rel, 1u);
        }
    }
}

// ===========================================================================
// t=0 layer-1 kernel (real-valued x, 3 fp16 limb products). Runs once.
// ===========================================================================
__global__ void __launch_bounds__(256, 2)
snn_tz(const __half* __restrict__ A0, const __half* __restrict__ A1,
       const __half* __restrict__ A2,
       const __half* __restrict__ W0, const __half* __restrict__ W1,
       const float* __restrict__ bias, float* __restrict__ mem,
       __half* __restrict__ spk, int N, int K)
{
    constexpr int FT = 16384;
    constexpr int FSTAGE = 5 * FT;
    extern __shared__ char smem[];
    const uint32_t sb = smem_u32(smem);

    const int tid = threadIdx.x, lane = tid & 31, wid = tid >> 5;
    const int wm = wid >> 2, wn = wid & 3;
    const int brow = blockIdx.y * 128, bcol = blockIdx.x * 128;

    const __half* Ap[3] = { A0 + (size_t)brow * K, A1 + (size_t)brow * K,
                            A2 + (size_t)brow * K };
    const __half* Wp[2] = { W0 + (size_t)bcol * K, W1 + (size_t)bcol * K };

    auto load_stage = [&](int st, int k0) {
        const uint32_t s0 = sb + st * FSTAGE;
#pragma unroll
        for (int l = 0; l < 3; l++) {
            const uint32_t d = s0 + l * FT;
            for (int q = tid; q < 1024; q += 256) {
                int r = q >> 3, c = q & 7;
                cp16(d + r * 128 + ((c ^ (r & 7)) << 4),
                     Ap[l] + (size_t)r * K + k0 + c * 8);
            }
        }
#pragma unroll
        for (int l = 0; l < 2; l++) {
            const uint32_t d = s0 + (3 + l) * FT;
            for (int q = tid; q < 1024; q += 256) {
                int r = q >> 3, c = q & 7;
                cp16(d + r * 128 + ((c ^ (r & 7)) << 4),
                     Wp[l] + (size_t)r * K + k0 + c * 8);
            }
        }
        asm volatile("cp.async.commit_group;" ::: "memory");
    };

    const int arow = (lane & 7) + 8 * ((lane >> 3) & 1);
    const int asel = lane >> 4;
    const int brw  = (lane & 7) + 8 * (lane >> 4);
    const int bsel = (lane >> 3) & 1;
    const int sx   = lane & 7;

    float acc[4][4][4];
#pragma unroll
    for (int i = 0; i < 4; i++)
#pragma unroll
        for (int j = 0; j < 4; j++)
#pragma unroll
            for (int k = 0; k < 4; k++) acc[i][j][k] = 0.0f;

    const int nch = K / 64;
    load_stage(0, 0);

    for (int ch = 0; ch < nch; ch++) {
        asm volatile("cp.async.wait_group 0;" ::: "memory");
        __syncthreads();
        if (ch + 1 < nch) load_stage((ch + 1) & 1, (ch + 1) * 64);

        const uint32_t s0 = sb + (ch & 1) * FSTAGE;
#pragma unroll
        for (int ks = 0; ks < 4; ks++) {
            const uint32_t aoff = ((2 * ks + asel) ^ sx) << 4;
            const uint32_t boff = ((2 * ks + bsel) ^ sx) << 4;
            uint32_t b[2][8];
#pragma unroll
            for (int w = 0; w < 2; w++) {
                const uint32_t bw = s0 + (3 + w) * FT + (wn * 32 + brw) * 128 + boff;
                ldsm4(bw, b[w][0], b[w][1], b[w][2], b[w][3]);
                ldsm4(bw + 16 * 128, b[w][4], b[w][5], b[w][6], b[w][7]);
            }
            const int PA[3] = {0, 1, 2}, PW[3] = {0, 1, 0};
#pragma unroll
            for (int p = 0; p < 3; p++) {
                uint32_t a[4][4];
#pragma unroll
                for (int mf = 0; mf < 4; mf++)
                    ldsm4(s0 + PA[p] * FT + (wm * 64 + mf * 16 + arow) * 128 + aoff,
                          a[mf][0], a[mf][1], a[mf][2], a[mf][3]);
#pragma unroll
                for (int mf = 0; mf < 4; mf++)
#pragma unroll
                    for (int nf = 0; nf < 4; nf++)
                        mma16816(acc[mf][nf], a[mf], b[PW[p]][2 * nf], b[PW[p]][2 * nf + 1]);
            }
        }
        __syncthreads();
    }

    const int qr = lane >> 2, qc = (lane & 3) * 2;
#pragma unroll
    for (int mf = 0; mf < 4; mf++)
#pragma unroll
    for (int h2 = 0; h2 < 2; h2++) {
        const int row = brow + wm * 64 + mf * 16 + qr + 8 * h2;
#pragma unroll
        for (int nf = 0; nf < 4; nf++) {
            const int col = bcol + wn * 32 + nf * 8 + qc;
            const size_t ix = (size_t)row * N + col;
            float2 bb = *reinterpret_cast<const float2*>(bias + col);
            float m0  = acc[mf][nf][2 * h2 + 0] + bb.x;
            float m1v = acc[mf][nf][2 * h2 + 1] + bb.y;
            const bool sp0 = m0 > THRV, sp1 = m1v > THRV;
            *reinterpret_cast<float2*>(mem + ix) = make_float2(m0, m1v);
            uint32_t sv = (sp0 ? 0x1000u : 0u) | (sp1 ? 0x10000000u : 0u);
            *reinterpret_cast<uint32_t*>(spk + ix) = sv;
        }
    }
}

// ---------------------------------------------------------------------------
// Fused prep: weight/x splits + Wo limbs (padded to 128 rows) + sched reset.
// ---------------------------------------------------------------------------
#define N_W1 (DIM_H1 * DIM_D)
#define N_W2 (DIM_H2 * DIM_H1)
#define N_X  (BATCH * DIM_D)
#define N_WO (128 * DIM_H2)

__global__ void __launch_bounds__(256)
prep_all(const float* __restrict__ W1, const float* __restrict__ W2,
         const float* __restrict__ x, const float* __restrict__ Wo,
         __half* __restrict__ w1h, __half* __restrict__ w1l,
         __half* __restrict__ w1hu,
         __half* __restrict__ w2h, __half* __restrict__ w2l,
         __half* __restrict__ xh, __half* __restrict__ xl,
         __half* __restrict__ xhs,
         __half* __restrict__ woh, __half* __restrict__ wol)
{
    if (blockIdx.x == 0) {
        for (int z = threadIdx.x; z < NUM_STEPS * RB_COUNT; z += 256) {
            (&g_cnt1[0][0])[z] = 0u;
            (&g_cnt2[0][0])[z] = 0u;
        }
        if (threadIdx.x == 0) g_ticket = 0u;
    }
    const int total = N_W1 + N_W2 + N_X + N_WO;
    for (int i = blockIdx.x * 256 + threadIdx.x; i < total; i += gridDim.x * 256) {
        if (i < N_W1) {
            float v = W1[i] * 2048.0f;
            __half h = __float2half_rn(v);
            w1h[i] = h;
            w1l[i] = __float2half_rn(v - __half2float(h));
            w1hu[i] = __float2half_rn(__half2float(h) * (1.0f / 2048.0f));
        } else if (i < N_W1 + N_W2) {
            int j = i - N_W1;
            float v = W2[j] * 2048.0f;
            __half h = __float2half_rn(v);
            w2h[j] = h;
            w2l[j] = __float2half_rn(v - __half2float(h));
        } else if (i < N_W1 + N_W2 + N_X) {
            int j = i - N_W1 - N_W2;
            float v = x[j];
            __half h = __float2half_rn(v);
            xh[j] = h;
            xl[j] = __float2half_rn(v - __half2float(h));
            xhs[j] = __float2half_rn(__half2float(h) * (1.0f / 2048.0f));
        } else {
            int j = i - N_W1 - N_W2 - N_X;
            int c = j >> 10;                    // row (0..127), k = j & 1023
            if (c < DIM_C) {
                float v = Wo[j] * 2048.0f;      // Wo is [64][1024] contiguous
                __half h = __float2half_rn(v);
                woh[j] = h;
                wol[j] = __float2half_rn(v - __half2float(h));
            } else {
                woh[j] = __float2half_rn(0.0f);
                wol[j] = __float2half_rn(0.0f);
            }
        }
    }
}

// ---------------------------------------------------------------------------
extern "C" void kernel_launch(void* const* d_in, const int* in_sizes, int n_in,
                              void* d_out, int out_size)
{
    const float* x  = (const float*)d_in[0];
    const float* W1 = (const float*)d_in[1];
    const float* b1 = (const float*)d_in[2];
    const float* W2 = (const float*)d_in[3];
    const float* b2 = (const float*)d_in[4];
    const float* Wo = (const float*)d_in[5];
    const float* bo = (const float*)d_in[6];
    float* out = (float*)d_out;

    auto sym = [](const void* s) { void* p; cudaGetSymbolAddress(&p, s); return p; };
    float*  m1   = (float*)sym(g_m1);
    float*  m2   = (float*)sym(g_m2);
    __half* spk  = (__half*)sym(g_spk);
    __half* s1   = (__half*)sym(g_s1);
    __half* s2   = (__half*)sym(g_s2);
    __half* w1h  = (__half*)sym(g_w1h);
    __half* w1l  = (__half*)sym(g_w1l);
    __half* w1hu = (__half*)sym(g_w1hu);
    __half* w2h  = (__half*)sym(g_w2h);
    __half* w2l  = (__half*)sym(g_w2l);
    __half* woh  = (__half*)sym(g_woh);
    __half* wol  = (__half*)sym(g_wol);
    __half* xh   = (__half*)sym(g_xh);
    __half* xl   = (__half*)sym(g_xl);
    __half* xhs  = (__half*)sym(g_xhs);

    constexpr int SM_PS = 1024 + 2 * 3 * 16384;   //  99328 -> 2 CTA/SM
    constexpr int SM_TZ = 2 * 5 * 16384;          // 163840 -> 1 CTA/SM
    cudaFuncSetAttribute(snn_tz, cudaFuncAttributeMaxDynamicSharedMemorySize, SM_TZ);
    cudaFuncSetAttribute(snn_persist, cudaFuncAttributeMaxDynamicSharedMemorySize, SM_PS);

    int nsm = 0, occ = 0;
    cudaDeviceGetAttribute(&nsm, cudaDevAttrMultiProcessorCount, 0);
    cudaOccupancyMaxActiveBlocksPerMultiprocessor(&occ, snn_persist, 256, SM_PS);
    if (occ < 1) occ = 1;
    if (occ > 2) occ = 2;
    const int pgrid = nsm * occ;

    prep_all<<<2048, 256>>>(W1, W2, x, Wo, w1h, w1l, w1hu, w2h, w2l,
                            xh, xl, xhs, woh, wol);

    dim3 gtz(DIM_H1 / 128, BATCH / 128);
    snn_tz<<<gtz, 256, SM_TZ>>>(xh, xhs, xl, w1hu, w1l, b1, m1, s1, DIM_H1, DIM_D);

    snn_persist<<<pgrid, 256, SM_PS>>>(w1h, w1l, w2h, w2l, b1, b2,
                                       m1, m2, s1, s2, spk,
                                       woh, wol, bo, out);
}

// round 13
// speedup vs baseline: 1.0820x; 1.0024x over previous
#include <cuda_runtime.h>
#include <cuda_fp16.h>
#include <cstdint>

// ===========================================================================
// SNN (20 steps, 2 fused Linear+LIF + feedback) on mma.sync (HMMA).
// Spikes = exactly 2^-11 in fp16; weights split into 2 fp16 limbs scaled by
// 2^11 -> products exact (fp32-identical trajectory).
// Round 13: R12 persistent kernel (proven 4282us) unchanged; TZ rebuilt as
// flat 3-phase / 3-stage / occ-2 pipeline; prep vectorized 4-wide.
// ===========================================================================

#define BATCH   4096
#define DIM_D   1024
#define DIM_H1  2048
#define DIM_H2  1024
#define DIM_C   64
#define NUM_STEPS 20
#define BETA 0.9f
#define THRV 1.0f

#define RB_COUNT 32
#define L1_CB 16
#define L2_CB 8
#define TILES_PER_STEP (RB_COUNT * (L1_CB + L2_CB))        // 768
#define TOT_TILES (RB_COUNT * L2_CB + (NUM_STEPS - 1) * TILES_PER_STEP)  // 14848
#define TOT_ALL (TOT_TILES + RB_COUNT)                      // +32 readout tiles

// ---------------------------------------------------------------------------
__device__ float  g_m1 [(size_t)BATCH * DIM_H1];
__device__ float  g_m2 [(size_t)BATCH * DIM_H2];
__device__ __half g_spk[(size_t)BATCH * DIM_H2];    // spike counts * 2^-11
__device__ __half g_s1 [(size_t)BATCH * DIM_H1];
__device__ __half g_s2 [(size_t)BATCH * DIM_H2];
__device__ __half g_w1h [(size_t)DIM_H1 * DIM_D];
__device__ __half g_w1l [(size_t)DIM_H1 * DIM_D];
__device__ __half g_w1hu[(size_t)DIM_H1 * DIM_D];
__device__ __half g_w2h [(size_t)DIM_H2 * DIM_H1];
__device__ __half g_w2l [(size_t)DIM_H2 * DIM_H1];
__device__ __half g_woh [(size_t)128 * DIM_H2];     // Wo*2^11 hi limb (padded)
__device__ __half g_wol [(size_t)128 * DIM_H2];     // Wo*2^11 lo limb (padded)
__device__ __half g_xh  [(size_t)BATCH * DIM_D];
__device__ __half g_xl  [(size_t)BATCH * DIM_D];
__device__ __half g_xhs [(size_t)BATCH * DIM_D];
__device__ unsigned g_ticket;
__device__ unsigned g_cnt1[NUM_STEPS][RB_COUNT];
__device__ unsigned g_cnt2[NUM_STEPS][RB_COUNT];

// ---------------------------------------------------------------------------
__device__ __forceinline__ uint32_t smem_u32(const void* p) {
    uint32_t a;
    asm("{ .reg .u64 t; cvta.to.shared.u64 t, %1; cvt.u32.u64 %0, t; }"
        : "=r"(a) : "l"(p));
    return a;
}
__device__ __forceinline__ void cp16(uint32_t dst, const void* src) {
    asm volatile("cp.async.cg.shared.global [%0], [%1], 16;"
                 :: "r"(dst), "l"(__cvta_generic_to_global(src)) : "memory");
}
__device__ __forceinline__ void ldsm4(uint32_t addr, uint32_t& r0, uint32_t& r1,
                                      uint32_t& r2, uint32_t& r3) {
    asm volatile("ldmatrix.sync.aligned.m8n8.x4.shared.b16 {%0,%1,%2,%3}, [%4];"
                 : "=r"(r0), "=r"(r1), "=r"(r2), "=r"(r3) : "r"(addr));
}
__device__ __forceinline__ void mma16816(float* c, const uint32_t a[4],
                                         uint32_t b0, uint32_t b1) {
    asm volatile(
        "mma.sync.aligned.m16n8k16.row.col.f32.f16.f16.f32 "
        "{%0,%1,%2,%3}, {%4,%5,%6,%7}, {%8,%9}, {%0,%1,%2,%3};"
        : "+f"(c[0]), "+f"(c[1]), "+f"(c[2]), "+f"(c[3])
        : "r"(a[0]), "r"(a[1]), "r"(a[2]), "r"(a[3]), "r"(b0), "r"(b1));
}

// ===========================================================================
// Persistent kernel (UNCHANGED from round 12): GEMM+LIF + readout tickets.
// layer: 1 = L1 GEMM+LIF, 2 = L2 GEMM+LIF(+sum), 3 = readout GEMM.
// ===========================================================================
__global__ void __launch_bounds__(256, 2)
snn_persist(const __half* __restrict__ w1h, const __half* __restrict__ w1l,
            const __half* __restrict__ w2h, const __half* __restrict__ w2l,
            const float* __restrict__ b1, const float* __restrict__ b2,
            float* __restrict__ m1, float* __restrict__ m2,
            __half* __restrict__ s1, __half* __restrict__ s2,
            __half* __restrict__ spk_sum,
            const __half* __restrict__ woh, const __half* __restrict__ wol,
            const float* __restrict__ bo, float* __restrict__ out)
{
    constexpr int TILE = 16384;
    constexpr int STAGE = 3 * TILE;
    extern __shared__ char smem[];
    unsigned* shdr = reinterpret_cast<unsigned*>(smem);
    const uint32_t sb = smem_u32(smem) + 1024;

    const int tid = threadIdx.x, lane = tid & 31, wid = tid >> 5;
    const int wm = wid >> 2, wn = wid & 3;

    const int arow = (lane & 7) + 8 * ((lane >> 3) & 1);
    const int asel = lane >> 4;
    const int brw  = (lane & 7) + 8 * (lane >> 4);
    const int bsel = (lane >> 3) & 1;
    const int sx   = lane & 7;
    const int qr   = lane >> 2, qc = (lane & 3) * 2;

    for (;;) {
        __syncthreads();
        if (tid == 0) shdr[0] = atomicAdd(&g_ticket, 1u);
        __syncthreads();
        const unsigned ti = shdr[0];
        if (ti >= TOT_ALL) break;

        int t, layer, rb, cb;
        if (ti >= TOT_TILES) {
            layer = 3; t = NUM_STEPS - 1; rb = (int)(ti - TOT_TILES); cb = 0;
        } else if (ti < RB_COUNT * L2_CB) {
            t = 0; layer = 2; rb = ti >> 3; cb = ti & 7;
        } else {
            const unsigned j = ti - RB_COUNT * L2_CB;
            t = 1 + (int)(j / TILES_PER_STEP);
            const unsigned r = j % TILES_PER_STEP;
            if (r < RB_COUNT * L1_CB) { layer = 1; rb = r >> 4; cb = r & 15; }
            else { const unsigned q = r - RB_COUNT * L1_CB; layer = 2; rb = q >> 3; cb = q & 7; }
        }

        if (tid == 0) {
            volatile unsigned* dep = nullptr;
            unsigned tgt = 0;
            if (layer == 1)      { dep = &g_cnt2[t - 1][rb]; tgt = L2_CB; }
            else if (layer == 3) { dep = &g_cnt2[NUM_STEPS - 1][rb]; tgt = L2_CB; }
            else if (t > 0)      { dep = &g_cnt1[t][rb];     tgt = L1_CB; }
            if (dep) while (*dep < tgt) __nanosleep(64);
        }
        __syncthreads();
        __threadfence();

        const int K = (layer == 2) ? DIM_H1 : DIM_H2;
        const __half* A  = (layer == 1) ? s2 : (layer == 2) ? s1 : spk_sum;
        const __half* W0 = (layer == 1) ? w1h : (layer == 2) ? w2h : woh;
        const __half* W1 = (layer == 1) ? w1l : (layer == 2) ? w2l : wol;
        const int brow = rb * 128, bcol = cb * 128;

        const __half* Ab = A + (size_t)brow * K;
        const __half* Wp0 = W0 + (size_t)bcol * K;
        const __half* Wp1 = W1 + (size_t)bcol * K;

        auto load_stage = [&](int st, int k0) {
            const uint32_t s0 = sb + st * STAGE;
            for (int q = tid; q < 1024; q += 256) {
                int r = q >> 3, c = q & 7;
                cp16(s0 + r * 128 + ((c ^ (r & 7)) << 4),
                     Ab + (size_t)r * K + k0 + c * 8);
            }
            for (int q = tid; q < 1024; q += 256) {
                int r = q >> 3, c = q & 7;
                cp16(s0 + TILE + r * 128 + ((c ^ (r & 7)) << 4),
                     Wp0 + (size_t)r * K + k0 + c * 8);
            }
            for (int q = tid; q < 1024; q += 256) {
                int r = q >> 3, c = q & 7;
                cp16(s0 + 2 * TILE + r * 128 + ((c ^ (r & 7)) << 4),
                     Wp1 + (size_t)r * K + k0 + c * 8);
            }
            asm volatile("cp.async.commit_group;" ::: "memory");
        };

        float acc[4][4][4];
#pragma unroll
        for (int i = 0; i < 4; i++)
#pragma unroll
            for (int j = 0; j < 4; j++)
#pragma unroll
                for (int k = 0; k < 4; k++) acc[i][j][k] = 0.0f;

        const int nch = K / 64;
        load_stage(0, 0);

        for (int ch = 0; ch < nch; ch++) {
            if (ch + 1 < nch) {
                load_stage((ch + 1) & 1, (ch + 1) * 64);
                asm volatile("cp.async.wait_group 1;" ::: "memory");
            } else {
                asm volatile("cp.async.wait_group 0;" ::: "memory");
            }
            __syncthreads();

            const uint32_t s0 = sb + (ch & 1) * STAGE;
            uint32_t bb[2][2];
#pragma unroll
            for (int w = 0; w < 2; w++)
#pragma unroll
                for (int h = 0; h < 2; h++)
                    bb[w][h] = s0 + (1 + w) * TILE + (wn * 32 + h * 16 + brw) * 128;

#pragma unroll
            for (int ks = 0; ks < 4; ks++) {
                uint32_t b[2][8];
#pragma unroll
                for (int w = 0; w < 2; w++) {
                    const uint32_t off = ((2 * ks + bsel) ^ sx) << 4;
                    ldsm4(bb[w][0] + off, b[w][0], b[w][1], b[w][2], b[w][3]);
                    ldsm4(bb[w][1] + off, b[w][4], b[w][5], b[w][6], b[w][7]);
                }
                const uint32_t aoff = ((2 * ks + asel) ^ sx) << 4;
                uint32_t a[4][4];
#pragma unroll
                for (int mf = 0; mf < 4; mf++)
                    ldsm4(s0 + (wm * 64 + mf * 16 + arow) * 128 + aoff,
                          a[mf][0], a[mf][1], a[mf][2], a[mf][3]);
#pragma unroll
                for (int w = 0; w < 2; w++)
#pragma unroll
                    for (int mf = 0; mf < 4; mf++)
#pragma unroll
                        for (int nf = 0; nf < 4; nf++)
                            mma16816(acc[mf][nf], a[mf], b[w][2 * nf], b[w][2 * nf + 1]);
            }
            __syncthreads();
        }

        if (layer == 3) {
#pragma unroll
            for (int mf = 0; mf < 4; mf++)
#pragma unroll
            for (int h = 0; h < 2; h++) {
                const int row = brow + wm * 64 + mf * 16 + qr + 8 * h;
#pragma unroll
                for (int nf = 0; nf < 4; nf++) {
                    const int col = wn * 32 + nf * 8 + qc;
                    if (col < DIM_C) {
                        float2 bb2 = *reinterpret_cast<const float2*>(bo + col);
                        float2 o;
                        o.x = acc[mf][nf][2 * h + 0] * (1.0f / NUM_STEPS) + bb2.x;
                        o.y = acc[mf][nf][2 * h + 1] * (1.0f / NUM_STEPS) + bb2.y;
                        *reinterpret_cast<float2*>(out + (size_t)row * DIM_C + col) = o;
                    }
                }
            }
            continue;
        }

        const int N = (layer == 1) ? DIM_H1 : DIM_H2;
        const float* bias = (layer == 1) ? b1 : b2;
        float* mem = (layer == 1) ? m1 : m2;
        __half* spko = (layer == 1) ? s1 : s2;
        const bool SUMf = (layer == 2);
        const bool FIRSTf = (layer == 2) && (t == 0);

#pragma unroll
        for (int mf = 0; mf < 4; mf++)
#pragma unroll
        for (int h = 0; h < 2; h++) {
            const int row = brow + wm * 64 + mf * 16 + qr + 8 * h;
#pragma unroll
            for (int nf = 0; nf < 4; nf++) {
                const int col = bcol + wn * 32 + nf * 8 + qc;
                const size_t ix = (size_t)row * N + col;
                float2 bb = *reinterpret_cast<const float2*>(bias + col);
                float v0 = acc[mf][nf][2 * h + 0] + bb.x;
                float v1 = acc[mf][nf][2 * h + 1] + bb.y;
                float m0, m1v;
                if (FIRSTf) {
                    m0 = v0; m1v = v1;
                } else {
                    float2 mo = *reinterpret_cast<const float2*>(mem + ix);
                    m0  = BETA * mo.x + v0 - ((mo.x > THRV) ? THRV : 0.0f);
                    m1v = BETA * mo.y + v1 - ((mo.y > THRV) ? THRV : 0.0f);
                }
                const bool sp0 = m0 > THRV, sp1 = m1v > THRV;
                *reinterpret_cast<float2*>(mem + ix) = make_float2(m0, m1v);
                uint32_t sv = (sp0 ? 0x1000u : 0u) | (sp1 ? 0x10000000u : 0u);
                *reinterpret_cast<uint32_t*>(spko + ix) = sv;
                if (SUMf) {
                    __half2 add;
                    uint32_t au = sv;
                    add = *reinterpret_cast<__half2*>(&au);
                    __half2* ss = reinterpret_cast<__half2*>(spk_sum + ix);
                    if (FIRSTf) *ss = add;
                    else        *ss = __hadd2(*ss, add);
                }
            }
        }

        __threadfence();
        __syncthreads();
        if (tid == 0) {
            unsigned* rel = (layer == 1) ? &g_cnt1[t][rb] : &g_cnt2[t][rb];
            atomicAdd(rel, 1u);
        }
    }
}

// ===========================================================================
// t=0 layer-1 kernel: flat 48-chunk loop (3 phases x 16 chunks), single
// product per chunk, 2-tile 32KB stages, 3-stage ring -> 96KB -> occ 2.
// Products: (xh, W0u), (xhs, W1), (xl, W0u); acc carried across phases.
// ===========================================================================
__global__ void __launch_bounds__(256, 2)
snn_tz(const __half* __restrict__ A0, const __half* __restrict__ A1,
       const __half* __restrict__ A2,
       const __half* __restrict__ W0, const __half* __restrict__ W1,
       const float* __restrict__ bias, float* __restrict__ mem,
       __half* __restrict__ spk, int N, int K)
{
    constexpr int TILE = 16384;
    constexpr int STAGE = 2 * TILE;     // A tile + W tile
    constexpr int NCH = 48;             // 3 phases x 16 chunks
    extern __shared__ char smem[];
    const uint32_t sb = smem_u32(smem);

    const int tid = threadIdx.x, lane = tid & 31, wid = tid >> 5;
    const int wm = wid >> 2, wn = wid & 3;
    const int brow = blockIdx.y * 128, bcol = blockIdx.x * 128;

    const __half* Ap[3] = { A0 + (size_t)brow * K, A1 + (size_t)brow * K,
                            A2 + (size_t)brow * K };
    const __half* Wp[2] = { W0 + (size_t)bcol * K, W1 + (size_t)bcol * K };

    auto load_stage = [&](int st, int ch) {
        const int p = ch >> 4, k0 = (ch & 15) * 64;
        const __half* As = Ap[p];
        const __half* Ws = Wp[(p == 1) ? 1 : 0];
        const uint32_t s0 = sb + st * STAGE;
        for (int q = tid; q < 1024; q += 256) {
            int r = q >> 3, c = q & 7;
            cp16(s0 + r * 128 + ((c ^ (r & 7)) << 4),
                 As + (size_t)r * K + k0 + c * 8);
        }
        for (int q = tid; q < 1024; q += 256) {
            int r = q >> 3, c = q & 7;
            cp16(s0 + TILE + r * 128 + ((c ^ (r & 7)) << 4),
                 Ws + (size_t)r * K + k0 + c * 8);
        }
        asm volatile("cp.async.commit_group;" ::: "memory");
    };

    const int arow = (lane & 7) + 8 * ((lane >> 3) & 1);
    const int asel = lane >> 4;
    const int brw  = (lane & 7) + 8 * (lane >> 4);
    const int bsel = (lane >> 3) & 1;
    const int sx   = lane & 7;

    float acc[4][4][4];
#pragma unroll
    for (int i = 0; i < 4; i++)
#pragma unroll
        for (int j = 0; j < 4; j++)
#pragma unroll
            for (int k = 0; k < 4; k++) acc[i][j][k] = 0.0f;

    load_stage(0, 0);
    load_stage(1, 1);

    for (int ch = 0; ch < NCH; ch++) {
        if (ch + 2 < NCH) {
            asm volatile("cp.async.wait_group 1;" ::: "memory");
        } else {
            asm volatile("cp.async.wait_group 0;" ::: "memory");
        }
        __syncthreads();
        if (ch + 2 < NCH) load_stage((ch + 2) % 3, ch + 2);

        const uint32_t s0 = sb + (ch % 3) * STAGE;
        const uint32_t bbase = s0 + TILE + (wn * 32 + brw) * 128;
#pragma unroll
        for (int ks = 0; ks < 4; ks++) {
            const uint32_t boff = ((2 * ks + bsel) ^ sx) << 4;
            uint32_t b[8];
            ldsm4(bbase + boff, b[0], b[1], b[2], b[3]);
            ldsm4(bbase + 16 * 128 + boff, b[4], b[5], b[6], b[7]);
            const uint32_t aoff = ((2 * ks + asel) ^ sx) << 4;
            uint32_t a[4][4];
#pragma unroll
            for (int mf = 0; mf < 4; mf++)
                ldsm4(s0 + (wm * 64 + mf * 16 + arow) * 128 + aoff,
                      a[mf][0], a[mf][1], a[mf][2], a[mf][3]);
#pragma unroll
            for (int mf = 0; mf < 4; mf++)
#pragma unroll
                for (int nf = 0; nf < 4; nf++)
                    mma16816(acc[mf][nf], a[mf], b[2 * nf], b[2 * nf + 1]);
        }
        __syncthreads();
    }

    const int qr = lane >> 2, qc = (lane & 3) * 2;
#pragma unroll
    for (int mf = 0; mf < 4; mf++)
#pragma unroll
    for (int h2 = 0; h2 < 2; h2++) {
        const int row = brow + wm * 64 + mf * 16 + qr + 8 * h2;
#pragma unroll
        for (int nf = 0; nf < 4; nf++) {
            const int col = bcol + wn * 32 + nf * 8 + qc;
            const size_t ix = (size_t)row * N + col;
            float2 bb = *reinterpret_cast<const float2*>(bias + col);
            float m0  = acc[mf][nf][2 * h2 + 0] + bb.x;
            float m1v = acc[mf][nf][2 * h2 + 1] + bb.y;
            const bool sp0 = m0 > THRV, sp1 = m1v > THRV;
            *reinterpret_cast<float2*>(mem + ix) = make_float2(m0, m1v);
            uint32_t sv = (sp0 ? 0x1000u : 0u) | (sp1 ? 0x10000000u : 0u);
            *reinterpret_cast<uint32_t*>(spk + ix) = sv;
        }
    }
}

// ---------------------------------------------------------------------------
// Fused prep (4-wide vectorized) + scheduler reset.
// ---------------------------------------------------------------------------
#define N_W1 (DIM_H1 * DIM_D)
#define N_W2 (DIM_H2 * DIM_H1)
#define N_X  (BATCH * DIM_D)
#define N_WO (128 * DIM_H2)

__global__ void __launch_bounds__(256)
prep_all(const float* __restrict__ W1, const float* __restrict__ W2,
         const float* __restrict__ x, const float* __restrict__ Wo,
         __half* __restrict__ w1h, __half* __restrict__ w1l,
         __half* __restrict__ w1hu,
         __half* __restrict__ w2h, __half* __restrict__ w2l,
         __half* __restrict__ xh, __half* __restrict__ xl,
         __half* __restrict__ xhs,
         __half* __restrict__ woh, __half* __restrict__ wol)
{
    if (blockIdx.x == 0) {
        for (int z = threadIdx.x; z < NUM_STEPS * RB_COUNT; z += 256) {
            (&g_cnt1[0][0])[z] = 0u;
            (&g_cnt2[0][0])[z] = 0u;
        }
        if (threadIdx.x == 0) g_ticket = 0u;
    }

    auto split2 = [](float4 v, float scale, __half* h, __half* l, int j) {
        float a0 = v.x * scale, a1 = v.y * scale, a2 = v.z * scale, a3 = v.w * scale;
        __half h0 = __float2half_rn(a0), h1 = __float2half_rn(a1);
        __half h2 = __float2half_rn(a2), h3 = __float2half_rn(a3);
        __half2 hh0 = __halves2half2(h0, h1), hh1 = __halves2half2(h2, h3);
        *reinterpret_cast<__half2*>(h + j)     = hh0;
        *reinterpret_cast<__half2*>(h + j + 2) = hh1;
        __half2 ll0 = __halves2half2(__float2half_rn(a0 - __half2float(h0)),
                                     __float2half_rn(a1 - __half2float(h1)));
        __half2 ll1 = __halves2half2(__float2half_rn(a2 - __half2float(h2)),
                                     __float2half_rn(a3 - __half2float(h3)));
        *reinterpret_cast<__half2*>(l + j)     = ll0;
        *reinterpret_cast<__half2*>(l + j + 2) = ll1;
    };

    const int total4 = (N_W1 + N_W2 + N_X + N_WO) / 4;
    for (int i4 = blockIdx.x * 256 + threadIdx.x; i4 < total4; i4 += gridDim.x * 256) {
        const int i = i4 * 4;
        if (i < N_W1) {
            float4 v = *reinterpret_cast<const float4*>(W1 + i);
            split2(v, 2048.0f, w1h, w1l, i);
            // unscaled hi limb for TZ product (xh, W0u)
            __half2 u0 = __halves2half2(
                __float2half_rn(__half2float(w1h[i + 0]) * (1.0f / 2048.0f)),
                __float2half_rn(__half2float(w1h[i + 1]) * (1.0f / 2048.0f)));
            __half2 u1 = __halves2half2(
                __float2half_rn(__half2float(w1h[i + 2]) * (1.0f / 2048.0f)),
                __float2half_rn(__half2float(w1h[i + 3]) * (1.0f / 2048.0f)));
            *reinterpret_cast<__half2*>(w1hu + i)     = u0;
            *reinterpret_cast<__half2*>(w1hu + i + 2) = u1;
        } else if (i < N_W1 + N_W2) {
            int j = i - N_W1;
            float4 v = *reinterpret_cast<const float4*>(W2 + j);
            split2(v, 2048.0f, w2h, w2l, j);
        } else if (i < N_W1 + N_W2 + N_X) {
            int j = i - N_W1 - N_W2;
            float4 v = *reinterpret_cast<const float4*>(x + j);
            float a[4] = {v.x, v.y, v.z, v.w};
            __half hh[4], hl[4], hs[4];
#pragma unroll
            for (int u = 0; u < 4; u++) {
                hh[u] = __float2half_rn(a[u]);
                hl[u] = __float2half_rn(a[u] - __half2float(hh[u]));
                hs[u] = __float2half_rn(__half2float(hh[u]) * (1.0f / 2048.0f));
            }
            *reinterpret_cast<__half2*>(xh + j)      = __halves2half2(hh[0], hh[1]);
            *reinterpret_cast<__half2*>(xh + j + 2)  = __halves2half2(hh[2], hh[3]);
            *reinterpret_cast<__half2*>(xl + j)      = __halves2half2(hl[0], hl[1]);
            *reinterpret_cast<__half2*>(xl + j + 2)  = __halves2half2(hl[2], hl[3]);
            *reinterpret_cast<__half2*>(xhs + j)     = __halves2half2(hs[0], hs[1]);
            *reinterpret_cast<__half2*>(xhs + j + 2) = __halves2half2(hs[2], hs[3]);
        } else {
            int j = i - N_W1 - N_W2 - N_X;
            int c = j >> 10;
            if (c < DIM_C) {
                float4 v = *reinterpret_cast<const float4*>(Wo + j);
                split2(v, 2048.0f, woh, wol, j);
            } else {
                __half2 z = __halves2half2(__float2half_rn(0.0f), __float2half_rn(0.0f));
                *reinterpret_cast<__half2*>(woh + j)     = z;
                *reinterpret_cast<__half2*>(woh + j + 2) = z;
                *reinterpret_cast<__half2*>(wol + j)     = z;
                *reinterpret_cast<__half2*>(wol + j + 2) = z;
            }
        }
    }
}

// ---------------------------------------------------------------------------
extern "C" void kernel_launch(void* const* d_in, const int* in_sizes, int n_in,
                              void* d_out, int out_size)
{
    const float* x  = (const float*)d_in[0];
    const float* W1 = (const float*)d_in[1];
    const float* b1 = (const float*)d_in[2];
    const float* W2 = (const float*)d_in[3];
    const float* b2 = (const float*)d_in[4];
    const float* Wo = (const float*)d_in[5];
    const float* bo = (const float*)d_in[6];
    float* out = (float*)d_out;

    auto sym = [](const void* s) { void* p; cudaGetSymbolAddress(&p, s); return p; };
    float*  m1   = (float*)sym(g_m1);
    float*  m2   = (float*)sym(g_m2);
    __half* spk  = (__half*)sym(g_spk);
    __half* s1   = (__half*)sym(g_s1);
    __half* s2   = (__half*)sym(g_s2);
    __half* w1h  = (__half*)sym(g_w1h);
    __half* w1l  = (__half*)sym(g_w1l);
    __half* w1hu = (__half*)sym(g_w1hu);
    __half* w2h  = (__half*)sym(g_w2h);
    __half* w2l  = (__half*)sym(g_w2l);
    __half* woh  = (__half*)sym(g_woh);
    __half* wol  = (__half*)sym(g_wol);
    __half* xh   = (__half*)sym(g_xh);
    __half* xl   = (__half*)sym(g_xl);
    __half* xhs  = (__half*)sym(g_xhs);

    constexpr int SM_PS = 1024 + 2 * 3 * 16384;   //  99328 -> 2 CTA/SM
    constexpr int SM_TZ = 3 * 2 * 16384;          //  98304 -> 2 CTA/SM
    cudaFuncSetAttribute(snn_tz, cudaFuncAttributeMaxDynamicSharedMemorySize, SM_TZ);
    cudaFuncSetAttribute(snn_persist, cudaFuncAttributeMaxDynamicSharedMemorySize, SM_PS);

    int nsm = 0, occ = 0;
    cudaDeviceGetAttribute(&nsm, cudaDevAttrMultiProcessorCount, 0);
    cudaOccupancyMaxActiveBlocksPerMultiprocessor(&occ, snn_persist, 256, SM_PS);
    if (occ < 1) occ = 1;
    if (occ > 2) occ = 2;
    const int pgrid = nsm * occ;

    prep_all<<<2048, 256>>>(W1, W2, x, Wo, w1h, w1l, w1hu, w2h, w2l,
                            xh, xl, xhs, woh, wol);

    dim3 gtz(DIM_H1 / 128, BATCH / 128);
    snn_tz<<<gtz, 256, SM_TZ>>>(xh, xhs, xl, w1hu, w1l, b1, m1, s1, DIM_H1, DIM_D);

    snn_persist<<<pgrid, 256, SM_PS>>>(w1h, w1l, w2h, w2l, b1, b2,
                                       m1, m2, s1, s2, spk,
                                       woh, wol, bo, out);
}

// round 14
// speedup vs baseline: 1.0892x; 1.0066x over previous
#include <cuda_runtime.h>
#include <cuda_fp16.h>
#include <cstdint>

// ===========================================================================
// SNN (20 steps, 2 fused Linear+LIF + feedback) on mma.sync (HMMA).
// Spikes = exactly 2^-11 in fp16; weights split into 2 fp16 limbs scaled by
// 2^11 -> products exact (fp32-identical trajectory).
// Round 14: TZ (t=0 layer-1, 3-product fp16) folded into the persistent
// kernel as layer-0 tickets -> fills TZ wave-quantization tail with L2-t0
// tiles and removes a launch boundary. Everything else from R13 (4272us).
// ===========================================================================

#define BATCH   4096
#define DIM_D   1024
#define DIM_H1  2048
#define DIM_H2  1024
#define DIM_C   64
#define NUM_STEPS 20
#define BETA 0.9f
#define THRV 1.0f

#define RB_COUNT 32
#define L1_CB 16
#define L2_CB 8
#define TOT_TZ (RB_COUNT * L1_CB)                           // 512
#define TILES_PER_STEP (RB_COUNT * (L1_CB + L2_CB))         // 768
#define TOT_STEADY (RB_COUNT * L2_CB + (NUM_STEPS - 1) * TILES_PER_STEP) // 14848
#define TOT_ALL (TOT_TZ + TOT_STEADY + RB_COUNT)            // 15392

// ---------------------------------------------------------------------------
__device__ float  g_m1 [(size_t)BATCH * DIM_H1];
__device__ float  g_m2 [(size_t)BATCH * DIM_H2];
__device__ __half g_spk[(size_t)BATCH * DIM_H2];    // spike counts * 2^-11
__device__ __half g_s1 [(size_t)BATCH * DIM_H1];
__device__ __half g_s2 [(size_t)BATCH * DIM_H2];
__device__ __half g_w1h [(size_t)DIM_H1 * DIM_D];
__device__ __half g_w1l [(size_t)DIM_H1 * DIM_D];
__device__ __half g_w1hu[(size_t)DIM_H1 * DIM_D];
__device__ __half g_w2h [(size_t)DIM_H2 * DIM_H1];
__device__ __half g_w2l [(size_t)DIM_H2 * DIM_H1];
__device__ __half g_woh [(size_t)128 * DIM_H2];     // Wo*2^11 hi limb (padded)
__device__ __half g_wol [(size_t)128 * DIM_H2];     // Wo*2^11 lo limb (padded)
__device__ __half g_xh  [(size_t)BATCH * DIM_D];
__device__ __half g_xl  [(size_t)BATCH * DIM_D];
__device__ __half g_xhs [(size_t)BATCH * DIM_D];
__device__ unsigned g_ticket;
__device__ unsigned g_cnt1[NUM_STEPS][RB_COUNT];    // cnt1[0] released by TZ
__device__ unsigned g_cnt2[NUM_STEPS][RB_COUNT];

// ---------------------------------------------------------------------------
__device__ __forceinline__ uint32_t smem_u32(const void* p) {
    uint32_t a;
    asm("{ .reg .u64 t; cvta.to.shared.u64 t, %1; cvt.u32.u64 %0, t; }"
        : "=r"(a) : "l"(p));
    return a;
}
__device__ __forceinline__ void cp16(uint32_t dst, const void* src) {
    asm volatile("cp.async.cg.shared.global [%0], [%1], 16;"
                 :: "r"(dst), "l"(__cvta_generic_to_global(src)) : "memory");
}
__device__ __forceinline__ void ldsm4(uint32_t addr, uint32_t& r0, uint32_t& r1,
                                      uint32_t& r2, uint32_t& r3) {
    asm volatile("ldmatrix.sync.aligned.m8n8.x4.shared.b16 {%0,%1,%2,%3}, [%4];"
                 : "=r"(r0), "=r"(r1), "=r"(r2), "=r"(r3) : "r"(addr));
}
__device__ __forceinline__ void mma16816(float* c, const uint32_t a[4],
                                         uint32_t b0, uint32_t b1) {
    asm volatile(
        "mma.sync.aligned.m16n8k16.row.col.f32.f16.f16.f32 "
        "{%0,%1,%2,%3}, {%4,%5,%6,%7}, {%8,%9}, {%0,%1,%2,%3};"
        : "+f"(c[0]), "+f"(c[1]), "+f"(c[2]), "+f"(c[3])
        : "r"(a[0]), "r"(a[1]), "r"(a[2]), "r"(a[3]), "r"(b0), "r"(b1));
}

// ===========================================================================
// Persistent kernel: TZ tiles (layer 0) + GEMM+LIF tiles (layer 1/2) +
// readout tiles (layer 3), one ticket queue.
// ===========================================================================
__global__ void __launch_bounds__(256, 2)
snn_persist(const __half* __restrict__ w1h, const __half* __restrict__ w1l,
            const __half* __restrict__ w2h, const __half* __restrict__ w2l,
            const float* __restrict__ b1, const float* __restrict__ b2,
            float* __restrict__ m1, float* __restrict__ m2,
            __half* __restrict__ s1, __half* __restrict__ s2,
            __half* __restrict__ spk_sum,
            const __half* __restrict__ woh, const __half* __restrict__ wol,
            const float* __restrict__ bo, float* __restrict__ out,
            const __half* __restrict__ xh, const __half* __restrict__ xhs,
            const __half* __restrict__ xl, const __half* __restrict__ w1hu)
{
    constexpr int TILE = 16384;
    constexpr int STAGE = 3 * TILE;          // steady: A + W0 + W1
    constexpr int STAGE2 = 2 * TILE;         // TZ: A-limb + W (3-stage ring)
    extern __shared__ char smem[];
    unsigned* shdr = reinterpret_cast<unsigned*>(smem);
    const uint32_t sb = smem_u32(smem) + 1024;

    const int tid = threadIdx.x, lane = tid & 31, wid = tid >> 5;
    const int wm = wid >> 2, wn = wid & 3;

    const int arow = (lane & 7) + 8 * ((lane >> 3) & 1);
    const int asel = lane >> 4;
    const int brw  = (lane & 7) + 8 * (lane >> 4);
    const int bsel = (lane >> 3) & 1;
    const int sx   = lane & 7;
    const int qr   = lane >> 2, qc = (lane & 3) * 2;

    for (;;) {
        __syncthreads();
        if (tid == 0) shdr[0] = atomicAdd(&g_ticket, 1u);
        __syncthreads();
        const unsigned ti = shdr[0];
        if (ti >= TOT_ALL) break;

        int t, layer, rb, cb;
        if (ti < TOT_TZ) {
            layer = 0; t = 0; rb = (int)(ti >> 4); cb = (int)(ti & 15);
        } else if (ti >= TOT_TZ + TOT_STEADY) {
            layer = 3; t = NUM_STEPS - 1; rb = (int)(ti - TOT_TZ - TOT_STEADY); cb = 0;
        } else if (ti < TOT_TZ + RB_COUNT * L2_CB) {
            const unsigned j = ti - TOT_TZ;
            t = 0; layer = 2; rb = j >> 3; cb = j & 7;
        } else {
            const unsigned j = ti - TOT_TZ - RB_COUNT * L2_CB;
            t = 1 + (int)(j / TILES_PER_STEP);
            const unsigned r = j % TILES_PER_STEP;
            if (r < RB_COUNT * L1_CB) { layer = 1; rb = r >> 4; cb = r & 15; }
            else { const unsigned q = r - RB_COUNT * L1_CB; layer = 2; rb = q >> 3; cb = q & 7; }
        }

        if (tid == 0) {
            volatile unsigned* dep = nullptr;
            unsigned tgt = 0;
            if (layer == 1)      { dep = &g_cnt2[t - 1][rb]; tgt = L2_CB; }
            else if (layer == 2) { dep = &g_cnt1[t][rb];     tgt = L1_CB; }
            else if (layer == 3) { dep = &g_cnt2[NUM_STEPS - 1][rb]; tgt = L2_CB; }
            if (dep) while (*dep < tgt) __nanosleep(64);
        }
        __syncthreads();
        __threadfence();

        const int brow = rb * 128, bcol = cb * 128;

        // =================== TZ TICKETS (layer 0) ===================
        if (layer == 0) {
            constexpr int NCH = 48;          // 3 phases x 16 chunks, K=1024
            const __half* Ap[3] = { xh  + (size_t)brow * DIM_D,
                                    xhs + (size_t)brow * DIM_D,
                                    xl  + (size_t)brow * DIM_D };
            const __half* Wp[2] = { w1hu + (size_t)bcol * DIM_D,
                                    w1l  + (size_t)bcol * DIM_D };

            auto load2 = [&](int st, int ch) {
                const int p = ch >> 4, k0 = (ch & 15) * 64;
                const __half* As = Ap[p];
                const __half* Ws = Wp[(p == 1) ? 1 : 0];
                const uint32_t s0 = sb + st * STAGE2;
                for (int q = tid; q < 1024; q += 256) {
                    int r = q >> 3, c = q & 7;
                    cp16(s0 + r * 128 + ((c ^ (r & 7)) << 4),
                         As + (size_t)r * DIM_D + k0 + c * 8);
                }
                for (int q = tid; q < 1024; q += 256) {
                    int r = q >> 3, c = q & 7;
                    cp16(s0 + TILE + r * 128 + ((c ^ (r & 7)) << 4),
                         Ws + (size_t)r * DIM_D + k0 + c * 8);
                }
                asm volatile("cp.async.commit_group;" ::: "memory");
            };

            float acc[4][4][4];
#pragma unroll
            for (int i = 0; i < 4; i++)
#pragma unroll
                for (int j = 0; j < 4; j++)
#pragma unroll
                    for (int k = 0; k < 4; k++) acc[i][j][k] = 0.0f;

            load2(0, 0);
            load2(1, 1);

            for (int ch = 0; ch < NCH; ch++) {
                if (ch + 2 < NCH)
                    asm volatile("cp.async.wait_group 1;" ::: "memory");
                else
                    asm volatile("cp.async.wait_group 0;" ::: "memory");
                __syncthreads();
                if (ch + 2 < NCH) load2((ch + 2) % 3, ch + 2);

                const uint32_t s0 = sb + (ch % 3) * STAGE2;
                const uint32_t bbase = s0 + TILE + (wn * 32 + brw) * 128;
#pragma unroll
                for (int ks = 0; ks < 4; ks++) {
                    const uint32_t boff = ((2 * ks + bsel) ^ sx) << 4;
                    uint32_t b[8];
                    ldsm4(bbase + boff, b[0], b[1], b[2], b[3]);
                    ldsm4(bbase + 16 * 128 + boff, b[4], b[5], b[6], b[7]);
                    const uint32_t aoff = ((2 * ks + asel) ^ sx) << 4;
                    uint32_t a[4][4];
#pragma unroll
                    for (int mf = 0; mf < 4; mf++)
                        ldsm4(s0 + (wm * 64 + mf * 16 + arow) * 128 + aoff,
                              a[mf][0], a[mf][1], a[mf][2], a[mf][3]);
#pragma unroll
                    for (int mf = 0; mf < 4; mf++)
#pragma unroll
                        for (int nf = 0; nf < 4; nf++)
                            mma16816(acc[mf][nf], a[mf], b[2 * nf], b[2 * nf + 1]);
                }
                __syncthreads();
            }

#pragma unroll
            for (int mf = 0; mf < 4; mf++)
#pragma unroll
            for (int h = 0; h < 2; h++) {
                const int row = brow + wm * 64 + mf * 16 + qr + 8 * h;
#pragma unroll
                for (int nf = 0; nf < 4; nf++) {
                    const int col = bcol + wn * 32 + nf * 8 + qc;
                    const size_t ix = (size_t)row * DIM_H1 + col;
                    float2 bb = *reinterpret_cast<const float2*>(b1 + col);
                    float m0  = acc[mf][nf][2 * h + 0] + bb.x;
                    float m1v = acc[mf][nf][2 * h + 1] + bb.y;
                    const bool sp0 = m0 > THRV, sp1 = m1v > THRV;
                    *reinterpret_cast<float2*>(m1 + ix) = make_float2(m0, m1v);
                    uint32_t sv = (sp0 ? 0x1000u : 0u) | (sp1 ? 0x10000000u : 0u);
                    *reinterpret_cast<uint32_t*>(s1 + ix) = sv;
                }
            }

            __threadfence();
            __syncthreads();
            if (tid == 0) atomicAdd(&g_cnt1[0][rb], 1u);
            continue;
        }

        // =================== STEADY / READOUT (shared mainloop) ===========
        const int K = (layer == 2) ? DIM_H1 : DIM_H2;
        const __half* A  = (layer == 1) ? s2 : (layer == 2) ? s1 : spk_sum;
        const __half* W0 = (layer == 1) ? w1h : (layer == 2) ? w2h : woh;
        const __half* W1 = (layer == 1) ? w1l : (layer == 2) ? w2l : wol;

        const __half* Ab = A + (size_t)brow * K;
        const __half* Wp0 = W0 + (size_t)bcol * K;
        const __half* Wp1 = W1 + (size_t)bcol * K;

        auto load_stage = [&](int st, int k0) {
            const uint32_t s0 = sb + st * STAGE;
            for (int q = tid; q < 1024; q += 256) {
                int r = q >> 3, c = q & 7;
                cp16(s0 + r * 128 + ((c ^ (r & 7)) << 4),
                     Ab + (size_t)r * K + k0 + c * 8);
            }
            for (int q = tid; q < 1024; q += 256) {
                int r = q >> 3, c = q & 7;
                cp16(s0 + TILE + r * 128 + ((c ^ (r & 7)) << 4),
                     Wp0 + (size_t)r * K + k0 + c * 8);
            }
            for (int q = tid; q < 1024; q += 256) {
                int r = q >> 3, c = q & 7;
                cp16(s0 + 2 * TILE + r * 128 + ((c ^ (r & 7)) << 4),
                     Wp1 + (size_t)r * K + k0 + c * 8);
            }
            asm volatile("cp.async.commit_group;" ::: "memory");
        };

        float acc[4][4][4];
#pragma unroll
        for (int i = 0; i < 4; i++)
#pragma unroll
            for (int j = 0; j < 4; j++)
#pragma unroll
                for (int k = 0; k < 4; k++) acc[i][j][k] = 0.0f;

        const int nch = K / 64;
        load_stage(0, 0);

        for (int ch = 0; ch < nch; ch++) {
            if (ch + 1 < nch) {
                load_stage((ch + 1) & 1, (ch + 1) * 64);
                asm volatile("cp.async.wait_group 1;" ::: "memory");
            } else {
                asm volatile("cp.async.wait_group 0;" ::: "memory");
            }
            __syncthreads();

            const uint32_t s0 = sb + (ch & 1) * STAGE;
            uint32_t bb[2][2];
#pragma unroll
            for (int w = 0; w < 2; w++)
#pragma unroll
                for (int h = 0; h < 2; h++)
                    bb[w][h] = s0 + (1 + w) * TILE + (wn * 32 + h * 16 + brw) * 128;

#pragma unroll
            for (int ks = 0; ks < 4; ks++) {
                uint32_t b[2][8];
#pragma unroll
                for (int w = 0; w < 2; w++) {
                    const uint32_t off = ((2 * ks + bsel) ^ sx) << 4;
                    ldsm4(bb[w][0] + off, b[w][0], b[w][1], b[w][2], b[w][3]);
                    ldsm4(bb[w][1] + off, b[w][4], b[w][5], b[w][6], b[w][7]);
                }
                const uint32_t aoff = ((2 * ks + asel) ^ sx) << 4;
                uint32_t a[4][4];
#pragma unroll
                for (int mf = 0; mf < 4; mf++)
                    ldsm4(s0 + (wm * 64 + mf * 16 + arow) * 128 + aoff,
                          a[mf][0], a[mf][1], a[mf][2], a[mf][3]);
#pragma unroll
                for (int w = 0; w < 2; w++)
#pragma unroll
                    for (int mf = 0; mf < 4; mf++)
#pragma unroll
                        for (int nf = 0; nf < 4; nf++)
                            mma16816(acc[mf][nf], a[mf], b[w][2 * nf], b[w][2 * nf + 1]);
            }
            __syncthreads();
        }

        if (layer == 3) {
#pragma unroll
            for (int mf = 0; mf < 4; mf++)
#pragma unroll
            for (int h = 0; h < 2; h++) {
                const int row = brow + wm * 64 + mf * 16 + qr + 8 * h;
#pragma unroll
                for (int nf = 0; nf < 4; nf++) {
                    const int col = wn * 32 + nf * 8 + qc;
                    if (col < DIM_C) {
                        float2 bb2 = *reinterpret_cast<const float2*>(bo + col);
                        float2 o;
                        o.x = acc[mf][nf][2 * h + 0] * (1.0f / NUM_STEPS) + bb2.x;
                        o.y = acc[mf][nf][2 * h + 1] * (1.0f / NUM_STEPS) + bb2.y;
                        *reinterpret_cast<float2*>(out + (size_t)row * DIM_C + col) = o;
                    }
                }
            }
            continue;
        }

        const int N = (layer == 1) ? DIM_H1 : DIM_H2;
        const float* bias = (layer == 1) ? b1 : b2;
        float* mem = (layer == 1) ? m1 : m2;
        __half* spko = (layer == 1) ? s1 : s2;
        const bool SUMf = (layer == 2);
        const bool FIRSTf = (layer == 2) && (t == 0);

#pragma unroll
        for (int mf = 0; mf < 4; mf++)
#pragma unroll
        for (int h = 0; h < 2; h++) {
            const int row = brow + wm * 64 + mf * 16 + qr + 8 * h;
#pragma unroll
            for (int nf = 0; nf < 4; nf++) {
                const int col = bcol + wn * 32 + nf * 8 + qc;
                const size_t ix = (size_t)row * N + col;
                float2 bb = *reinterpret_cast<const float2*>(bias + col);
                float v0 = acc[mf][nf][2 * h + 0] + bb.x;
                float v1 = acc[mf][nf][2 * h + 1] + bb.y;
                float m0, m1v;
                if (FIRSTf) {
                    m0 = v0; m1v = v1;
                } else {
                    float2 mo = *reinterpret_cast<const float2*>(mem + ix);
                    m0  = BETA * mo.x + v0 - ((mo.x > THRV) ? THRV : 0.0f);
                    m1v = BETA * mo.y + v1 - ((mo.y > THRV) ? THRV : 0.0f);
                }
                const bool sp0 = m0 > THRV, sp1 = m1v > THRV;
                *reinterpret_cast<float2*>(mem + ix) = make_float2(m0, m1v);
                uint32_t sv = (sp0 ? 0x1000u : 0u) | (sp1 ? 0x10000000u : 0u);
                *reinterpret_cast<uint32_t*>(spko + ix) = sv;
                if (SUMf) {
                    __half2 add;
                    uint32_t au = sv;
                    add = *reinterpret_cast<__half2*>(&au);
                    __half2* ss = reinterpret_cast<__half2*>(spk_sum + ix);
                    if (FIRSTf) *ss = add;
                    else        *ss = __hadd2(*ss, add);
                }
            }
        }

        __threadfence();
        __syncthreads();
        if (tid == 0) {
            unsigned* rel = (layer == 1) ? &g_cnt1[t][rb] : &g_cnt2[t][rb];
            atomicAdd(rel, 1u);
        }
    }
}

// ---------------------------------------------------------------------------
// Fused prep (4-wide vectorized) + scheduler reset.
// ---------------------------------------------------------------------------
#define N_W1 (DIM_H1 * DIM_D)
#define N_W2 (DIM_H2 * DIM_H1)
#define N_X  (BATCH * DIM_D)
#define N_WO (128 * DIM_H2)

__global__ void __launch_bounds__(256)
prep_all(const float* __restrict__ W1, const float* __restrict__ W2,
         const float* __restrict__ x, const float* __restrict__ Wo,
         __half* __restrict__ w1h, __half* __restrict__ w1l,
         __half* __restrict__ w1hu,
         __half* __restrict__ w2h, __half* __restrict__ w2l,
         __half* __restrict__ xh, __half* __restrict__ xl,
         __half* __restrict__ xhs,
         __half* __restrict__ woh, __half* __restrict__ wol)
{
    if (blockIdx.x == 0) {
        for (int z = threadIdx.x; z < NUM_STEPS * RB_COUNT; z += 256) {
            (&g_cnt1[0][0])[z] = 0u;
            (&g_cnt2[0][0])[z] = 0u;
        }
        if (threadIdx.x == 0) g_ticket = 0u;
    }

    auto split2 = [](float4 v, float scale, __half* h, __half* l, int j) {
        float a0 = v.x * scale, a1 = v.y * scale, a2 = v.z * scale, a3 = v.w * scale;
        __half h0 = __float2half_rn(a0), h1 = __float2half_rn(a1);
        __half h2 = __float2half_rn(a2), h3 = __float2half_rn(a3);
        *reinterpret_cast<__half2*>(h + j)     = __halves2half2(h0, h1);
        *reinterpret_cast<__half2*>(h + j + 2) = __halves2half2(h2, h3);
        *reinterpret_cast<__half2*>(l + j) =
            __halves2half2(__float2half_rn(a0 - __half2float(h0)),
                           __float2half_rn(a1 - __half2float(h1)));
        *reinterpret_cast<__half2*>(l + j + 2) =
            __halves2half2(__float2half_rn(a2 - __half2float(h2)),
                           __float2half_rn(a3 - __half2float(h3)));
    };

    const int total4 = (N_W1 + N_W2 + N_X + N_WO) / 4;
    for (int i4 = blockIdx.x * 256 + threadIdx.x; i4 < total4; i4 += gridDim.x * 256) {
        const int i = i4 * 4;
        if (i < N_W1) {
            float4 v = *reinterpret_cast<const float4*>(W1 + i);
            split2(v, 2048.0f, w1h, w1l, i);
            *reinterpret_cast<__half2*>(w1hu + i) = __halves2half2(
                __float2half_rn(__half2float(w1h[i + 0]) * (1.0f / 2048.0f)),
                __float2half_rn(__half2float(w1h[i + 1]) * (1.0f / 2048.0f)));
            *reinterpret_cast<__half2*>(w1hu + i + 2) = __halves2half2(
                __float2half_rn(__half2float(w1h[i + 2]) * (1.0f / 2048.0f)),
                __float2half_rn(__half2float(w1h[i + 3]) * (1.0f / 2048.0f)));
        } else if (i < N_W1 + N_W2) {
            int j = i - N_W1;
            float4 v = *reinterpret_cast<const float4*>(W2 + j);
            split2(v, 2048.0f, w2h, w2l, j);
        } else if (i < N_W1 + N_W2 + N_X) {
            int j = i - N_W1 - N_W2;
            float4 v = *reinterpret_cast<const float4*>(x + j);
            float a[4] = {v.x, v.y, v.z, v.w};
            __half hh[4], hl[4], hs[4];
#pragma unroll
            for (int u = 0; u < 4; u++) {
                hh[u] = __float2half_rn(a[u]);
                hl[u] = __float2half_rn(a[u] - __half2float(hh[u]));
                hs[u] = __float2half_rn(__half2float(hh[u]) * (1.0f / 2048.0f));
            }
            *reinterpret_cast<__half2*>(xh + j)      = __halves2half2(hh[0], hh[1]);
            *reinterpret_cast<__half2*>(xh + j + 2)  = __halves2half2(hh[2], hh[3]);
            *reinterpret_cast<__half2*>(xl + j)      = __halves2half2(hl[0], hl[1]);
            *reinterpret_cast<__half2*>(xl + j + 2)  = __halves2half2(hl[2], hl[3]);
            *reinterpret_cast<__half2*>(xhs + j)     = __halves2half2(hs[0], hs[1]);
            *reinterpret_cast<__half2*>(xhs + j + 2) = __halves2half2(hs[2], hs[3]);
        } else {
            int j = i - N_W1 - N_W2 - N_X;
            int c = j >> 10;
            if (c < DIM_C) {
                float4 v = *reinterpret_cast<const float4*>(Wo + j);
                split2(v, 2048.0f, woh, wol, j);
            } else {
                __half2 z = __halves2half2(__float2half_rn(0.0f), __float2half_rn(0.0f));
                *reinterpret_cast<__half2*>(woh + j)     = z;
                *reinterpret_cast<__half2*>(woh + j + 2) = z;
                *reinterpret_cast<__half2*>(wol + j)     = z;
                *reinterpret_cast<__half2*>(wol + j + 2) = z;
            }
        }
    }
}

// ---------------------------------------------------------------------------
extern "C" void kernel_launch(void* const* d_in, const int* in_sizes, int n_in,
                              void* d_out, int out_size)
{
    const float* x  = (const float*)d_in[0];
    const float* W1 = (const float*)d_in[1];
    const float* b1 = (const float*)d_in[2];
    const float* W2 = (const float*)d_in[3];
    const float* b2 = (const float*)d_in[4];
    const float* Wo = (const float*)d_in[5];
    const float* bo = (const float*)d_in[6];
    float* out = (float*)d_out;

    auto sym = [](const void* s) { void* p; cudaGetSymbolAddress(&p, s); return p; };
    float*  m1   = (float*)sym(g_m1);
    float*  m2   = (float*)sym(g_m2);
    __half* spk  = (__half*)sym(g_spk);
    __half* s1   = (__half*)sym(g_s1);
    __half* s2   = (__half*)sym(g_s2);
    __half* w1h  = (__half*)sym(g_w1h);
    __half* w1l  = (__half*)sym(g_w1l);
    __half* w1hu = (__half*)sym(g_w1hu);
    __half* w2h  = (__half*)sym(g_w2h);
    __half* w2l  = (__half*)sym(g_w2l);
    __half* woh  = (__half*)sym(g_woh);
    __half* wol  = (__half*)sym(g_wol);
    __half* xh   = (__half*)sym(g_xh);
    __half* xl   = (__half*)sym(g_xl);
    __half* xhs  = (__half*)sym(g_xhs);

    constexpr int SM_PS = 1024 + 2 * 3 * 16384;   //  99328 -> 2 CTA/SM
    cudaFuncSetAttribute(snn_persist, cudaFuncAttributeMaxDynamicSharedMemorySize, SM_PS);

    int nsm = 0, occ = 0;
    cudaDeviceGetAttribute(&nsm, cudaDevAttrMultiProcessorCount, 0);
    cudaOccupancyMaxActiveBlocksPerMultiprocessor(&occ, snn_persist, 256, SM_PS);
    if (occ < 1) occ = 1;
    if (occ > 2) occ = 2;
    const int pgrid = nsm * occ;

    prep_all<<<2048, 256>>>(W1, W2, x, Wo, w1h, w1l, w1hu, w2h, w2l,
                            xh, xl, xhs, woh, wol);

    snn_persist<<<pgrid, 256, SM_PS>>>(w1h, w1l, w2h, w2l, b1, b2,
                                       m1, m2, s1, s2, spk,
                                       woh, wol, bo, out,
                                       xh, xhs, xl, w1hu);
}